// round 1
// baseline (speedup 1.0000x reference)
#include <cuda_runtime.h>
#include <cuda_bf16.h>
#include <math.h>

// Problem dims (fixed by reference)
#define BB 2
#define SS 2048
#define DD 1024
#define HH 16
#define HDD 64
#define II 3752
#define MM (BB * SS)   // 4096 rows

// ---------------- scratch (device globals; no allocation) ----------------
__device__ float g_h   [MM * DD];
__device__ float g_q   [MM * DD];
__device__ float g_k   [MM * DD];
__device__ float g_v   [MM * DD];
__device__ float g_attn[MM * DD];
__device__ float g_res1[MM * DD];
__device__ float g_h2  [MM * DD];
__device__ float g_gate[(size_t)MM * II];
__device__ float g_up  [(size_t)MM * II];

// ---------------- RMSNorm: one block per row, 256 threads ----------------
__global__ __launch_bounds__(256)
void rmsnorm_kernel(const float* __restrict__ x, const float* __restrict__ w,
                    float* __restrict__ out)
{
    int row = blockIdx.x;
    const float* xr = x + (size_t)row * DD;
    float* orow = out + (size_t)row * DD;
    int t = threadIdx.x;

    float v0 = xr[t];
    float v1 = xr[t + 256];
    float v2 = xr[t + 512];
    float v3 = xr[t + 768];
    float ss = v0*v0 + v1*v1 + v2*v2 + v3*v3;

    #pragma unroll
    for (int off = 16; off; off >>= 1)
        ss += __shfl_xor_sync(0xffffffffu, ss, off);

    __shared__ float red[8];
    int wid = t >> 5, lid = t & 31;
    if (lid == 0) red[wid] = ss;
    __syncthreads();
    float tot = red[0] + red[1] + red[2] + red[3] + red[4] + red[5] + red[6] + red[7];
    float inv = rsqrtf(tot * (1.0f / (float)DD) + 1e-6f);

    orow[t]       = w[t]       * v0 * inv;
    orow[t + 256] = w[t + 256] * v1 * inv;
    orow[t + 512] = w[t + 512] * v2 * inv;
    orow[t + 768] = w[t + 768] * v3 * inv;
}

// ---------------- generic fp32 SGEMM: C = A@B (+bias) (+add) ----------------
// A [M,K] row-major, B [K,N] row-major, C [M,N].
// 128x128 block tile, BK=16, 256 threads, 8x8 per thread.
#define BM 128
#define BN 128
#define BK 16

__global__ __launch_bounds__(256)
void sgemm_kernel(const float* __restrict__ A, const float* __restrict__ B,
                  const float* __restrict__ bias, const float* __restrict__ add,
                  float* __restrict__ C, int M, int N, int K)
{
    __shared__ float As[BK][BM];
    __shared__ float Bs[BK][BN];

    int tid = threadIdx.x;
    int bm = blockIdx.y * BM;
    int bn = blockIdx.x * BN;

    int ty = tid / 16;           // 0..15
    int tx = tid % 16;           // 0..15

    float acc[8][8];
    #pragma unroll
    for (int i = 0; i < 8; i++)
        #pragma unroll
        for (int j = 0; j < 8; j++) acc[i][j] = 0.0f;

    int arow = tid / 4;          // 0..63 (+64)
    int acol = (tid % 4) * 4;    // 0,4,8,12
    int brow = tid / 32;         // 0..7 (+8)
    int bcol = (tid % 32) * 4;   // 0..124

    int ktiles = (K + BK - 1) / BK;
    for (int kt = 0; kt < ktiles; kt++) {
        int k0 = kt * BK;

        // load A tile (transposed into As)
        #pragma unroll
        for (int i = 0; i < 2; i++) {
            int r = arow + i * 64;
            int gk = k0 + acol;
            const float* ap = A + (size_t)(bm + r) * K + gk;
            float4 a = make_float4(0.f, 0.f, 0.f, 0.f);
            if (gk + 3 < K) {
                a = *(const float4*)ap;
            } else {
                if (gk     < K) a.x = ap[0];
                if (gk + 1 < K) a.y = ap[1];
                if (gk + 2 < K) a.z = ap[2];
                if (gk + 3 < K) a.w = ap[3];
            }
            As[acol + 0][r] = a.x;
            As[acol + 1][r] = a.y;
            As[acol + 2][r] = a.z;
            As[acol + 3][r] = a.w;
        }
        // load B tile
        #pragma unroll
        for (int i = 0; i < 2; i++) {
            int rk = k0 + brow + i * 8;
            int gc = bn + bcol;
            float4 bv = make_float4(0.f, 0.f, 0.f, 0.f);
            if (rk < K) {
                const float* bp = B + (size_t)rk * N + gc;
                if (gc + 3 < N) {
                    bv = *(const float4*)bp;
                } else {
                    if (gc     < N) bv.x = bp[0];
                    if (gc + 1 < N) bv.y = bp[1];
                    if (gc + 2 < N) bv.z = bp[2];
                }
            }
            *(float4*)&Bs[brow + i * 8][bcol] = bv;
        }
        __syncthreads();

        #pragma unroll
        for (int kk = 0; kk < BK; kk++) {
            float a[8], b[8];
            #pragma unroll
            for (int i = 0; i < 8; i++) a[i] = As[kk][ty * 8 + i];
            #pragma unroll
            for (int j = 0; j < 8; j++) b[j] = Bs[kk][tx * 8 + j];
            #pragma unroll
            for (int i = 0; i < 8; i++)
                #pragma unroll
                for (int j = 0; j < 8; j++)
                    acc[i][j] += a[i] * b[j];
        }
        __syncthreads();
    }

    // epilogue
    #pragma unroll
    for (int i = 0; i < 8; i++) {
        int r = bm + ty * 8 + i;
        #pragma unroll
        for (int j = 0; j < 8; j++) {
            int c = bn + tx * 8 + j;
            if (c < N) {
                float v = acc[i][j];
                if (bias) v += bias[c];
                if (add)  v += add[(size_t)r * N + c];
                C[(size_t)r * N + c] = v;
            }
        }
    }
}

// ---------------- flash attention (fp32, causal + alibi + key padding) ------
// One thread per query row; 128 query rows per block; K/V tiles of 32 in smem.
#define AT_KT 32

__global__ __launch_bounds__(128)
void attn_kernel(const float* __restrict__ q, const float* __restrict__ k,
                 const float* __restrict__ v, const unsigned char* __restrict__ kpm,
                 float* __restrict__ out)
{
    int bh = blockIdx.y;
    int b = bh / HH, h = bh % HH;
    int qi = blockIdx.x * 128 + threadIdx.x;   // query row 0..S-1

    __shared__ float ks[AT_KT][HDD];
    __shared__ float vs[AT_KT][HDD];
    __shared__ unsigned char kpms[AT_KT];

    // load q row into registers
    float qr[HDD];
    const float* qp = q + (size_t)(b * SS + qi) * DD + h * HDD;
    #pragma unroll
    for (int d = 0; d < HDD; d += 4) {
        float4 t = *(const float4*)(qp + d);
        qr[d] = t.x; qr[d+1] = t.y; qr[d+2] = t.z; qr[d+3] = t.w;
    }

    float slope = -exp2f(-0.5f * (float)(h + 1));
    float m = -INFINITY, l = 0.0f;
    float o[HDD];
    #pragma unroll
    for (int d = 0; d < HDD; d++) o[d] = 0.0f;

    int qmax = blockIdx.x * 128 + 127;
    int ntiles = qmax / AT_KT + 1;

    for (int t = 0; t < ntiles; t++) {
        int j0 = t * AT_KT;
        __syncthreads();
        // cooperative K/V tile load: 32x64 floats each; 128 threads x 4 float4
        for (int i = threadIdx.x; i < AT_KT * (HDD / 4); i += 128) {
            int row = i / (HDD / 4);
            int c4  = i % (HDD / 4);
            size_t base = (size_t)(b * SS + j0 + row) * DD + h * HDD + c4 * 4;
            ((float4*)ks[row])[c4] = *(const float4*)(k + base);
            ((float4*)vs[row])[c4] = *(const float4*)(v + base);
        }
        if (threadIdx.x < AT_KT)
            kpms[threadIdx.x] = kpm[b * SS + j0 + threadIdx.x];
        __syncthreads();

        float s[AT_KT];
        float tmax = -INFINITY;
        #pragma unroll
        for (int j = 0; j < AT_KT; j++) {
            int jj = j0 + j;
            float acc = 0.0f;
            #pragma unroll
            for (int d4 = 0; d4 < HDD / 4; d4++) {
                float4 kv = ((const float4*)ks[j])[d4];
                acc += qr[d4*4+0] * kv.x;
                acc += qr[d4*4+1] * kv.y;
                acc += qr[d4*4+2] * kv.z;
                acc += qr[d4*4+3] * kv.w;
            }
            float sc = acc * 0.125f + slope * fabsf((float)(qi - jj));
            if (jj > qi || kpms[j]) sc = -INFINITY;
            s[j] = sc;
            tmax = fmaxf(tmax, sc);
        }
        if (tmax > -INFINITY) {
            float mnew = fmaxf(m, tmax);
            float corr = __expf(m - mnew);   // m = -inf initially -> 0
            l *= corr;
            #pragma unroll
            for (int d = 0; d < HDD; d++) o[d] *= corr;
            m = mnew;
            #pragma unroll
            for (int j = 0; j < AT_KT; j++) {
                float p = __expf(s[j] - m);  // -inf -> 0
                l += p;
                #pragma unroll
                for (int d4 = 0; d4 < HDD / 4; d4++) {
                    float4 vv = ((const float4*)vs[j])[d4];
                    o[d4*4+0] += p * vv.x;
                    o[d4*4+1] += p * vv.y;
                    o[d4*4+2] += p * vv.z;
                    o[d4*4+3] += p * vv.w;
                }
            }
        }
    }

    float inv = 1.0f / l;
    float* op = out + (size_t)(b * SS + qi) * DD + h * HDD;
    #pragma unroll
    for (int d = 0; d < HDD; d += 4) {
        float4 t;
        t.x = o[d] * inv; t.y = o[d+1] * inv; t.z = o[d+2] * inv; t.w = o[d+3] * inv;
        *(float4*)(op + d) = t;
    }
}

// ---------------- SwiGLU elementwise: g = silu(g) * u ----------------
__global__ __launch_bounds__(256)
void silu_mul_kernel(float* __restrict__ g, const float* __restrict__ u, size_t n)
{
    size_t i = (size_t)blockIdx.x * blockDim.x + threadIdx.x;
    size_t stride = (size_t)gridDim.x * blockDim.x;
    for (; i < n; i += stride) {
        float x = g[i];
        float sig = 1.0f / (1.0f + __expf(-x));
        g[i] = x * sig * u[i];
    }
}

// ---------------- launch ----------------
extern "C" void kernel_launch(void* const* d_in, const int* in_sizes, int n_in,
                              void* d_out, int out_size)
{
    const float* x      = (const float*)d_in[0];
    const float* wq     = (const float*)d_in[1];
    const float* bq     = (const float*)d_in[2];
    const float* wk     = (const float*)d_in[3];
    const float* bk     = (const float*)d_in[4];
    const float* wv     = (const float*)d_in[5];
    const float* bv     = (const float*)d_in[6];
    const float* wo     = (const float*)d_in[7];
    const float* bo     = (const float*)d_in[8];
    const float* w_gate = (const float*)d_in[9];
    const float* w_up   = (const float*)d_in[10];
    const float* w_down = (const float*)d_in[11];
    const float* ln1w   = (const float*)d_in[12];
    const float* ln2w   = (const float*)d_in[13];
    // d_in[14] attn_bias (computed analytically), d_in[15] tgt_mask (causal, analytic)
    const unsigned char* kpm = (const unsigned char*)d_in[16];
    float* out = (float*)d_out;

    float *h, *q, *k, *v, *attn, *res1, *h2, *gate, *up;
    cudaGetSymbolAddress((void**)&h,    g_h);
    cudaGetSymbolAddress((void**)&q,    g_q);
    cudaGetSymbolAddress((void**)&k,    g_k);
    cudaGetSymbolAddress((void**)&v,    g_v);
    cudaGetSymbolAddress((void**)&attn, g_attn);
    cudaGetSymbolAddress((void**)&res1, g_res1);
    cudaGetSymbolAddress((void**)&h2,   g_h2);
    cudaGetSymbolAddress((void**)&gate, g_gate);
    cudaGetSymbolAddress((void**)&up,   g_up);

    // 1) h = rmsnorm(x, ln1_w)
    rmsnorm_kernel<<<MM, 256>>>(x, ln1w, h);

    // 2) q,k,v = h@W + b
    dim3 gD((DD + BN - 1) / BN, MM / BM);
    sgemm_kernel<<<gD, 256>>>(h, wq, bq, nullptr, q, MM, DD, DD);
    sgemm_kernel<<<gD, 256>>>(h, wk, bk, nullptr, k, MM, DD, DD);
    sgemm_kernel<<<gD, 256>>>(h, wv, bv, nullptr, v, MM, DD, DD);

    // 3) attention (causal + alibi + key padding), flash-style
    attn_kernel<<<dim3(SS / 128, BB * HH), 128>>>(q, k, v, kpm, attn);

    // 4) res1 = attn@wo + bo + x
    sgemm_kernel<<<gD, 256>>>(attn, wo, bo, x, res1, MM, DD, DD);

    // 5) h2 = rmsnorm(res1, ln2_w)
    rmsnorm_kernel<<<MM, 256>>>(res1, ln2w, h2);

    // 6) gate = h2@w_gate ; up = h2@w_up
    dim3 gI((II + BN - 1) / BN, MM / BM);
    sgemm_kernel<<<gI, 256>>>(h2, w_gate, nullptr, nullptr, gate, MM, II, DD);
    sgemm_kernel<<<gI, 256>>>(h2, w_up,   nullptr, nullptr, up,   MM, II, DD);

    // 7) gate = silu(gate) * up
    silu_mul_kernel<<<2048, 256>>>(gate, up, (size_t)MM * II);

    // 8) out = gate@w_down + res1
    sgemm_kernel<<<gD, 256>>>(gate, w_down, nullptr, res1, out, MM, DD, II);

    (void)in_sizes; (void)n_in; (void)out_size;
}

// round 4
// speedup vs baseline: 1.9074x; 1.9074x over previous
#include <cuda_runtime.h>
#include <cuda_bf16.h>
#include <math.h>
#include <stdint.h>

// ---------------- problem dims ----------------
#define BB 2
#define SS 2048
#define DD 1024
#define HH 16
#define HDD 64
#define II 3752
#define MM (BB*SS)          // 4096
#define QKVN 3072
#define IPAD 3840           // I padded to multiple of 128
#define GUN (2*IPAD)        // 7680 fused gate|up

// ---------------- scratch (device globals; no allocation) ----------------
__device__ __nv_bfloat16 g_h_hi[MM*DD],  g_h_lo[MM*DD];
__device__ float         g_qkv[(size_t)MM*QKVN];
__device__ __nv_bfloat16 g_attn_hi[MM*DD], g_attn_lo[MM*DD];
__device__ float         g_res1[MM*DD];
__device__ __nv_bfloat16 g_h2_hi[MM*DD], g_h2_lo[MM*DD];
__device__ float         g_gu[(size_t)MM*GUN];
__device__ __nv_bfloat16 g_act_hi[(size_t)MM*IPAD], g_act_lo[(size_t)MM*IPAD];
// weights: transposed ([N,K] K-major) + split
__device__ __nv_bfloat16 g_wqkvT_hi[QKVN*DD], g_wqkvT_lo[QKVN*DD];
__device__ __nv_bfloat16 g_woT_hi[DD*DD],     g_woT_lo[DD*DD];
__device__ __nv_bfloat16 g_wguT_hi[GUN*DD],   g_wguT_lo[GUN*DD];
__device__ __nv_bfloat16 g_wdT_hi[DD*IPAD],   g_wdT_lo[DD*IPAD];
__device__ float         g_bqkv[QKVN];

// ---------------- helpers ----------------
__device__ __forceinline__ uint32_t smem_u32(const void* p){
    uint32_t r;
    asm("{ .reg .u64 t; cvta.to.shared.u64 t, %1; cvt.u32.u64 %0, t; }" : "=r"(r) : "l"(p));
    return r;
}
#define SWZ64(x) ((x) ^ (((x) >> 3) & 0x30))

__device__ __forceinline__ void ldsm_x4(uint32_t* r, uint32_t a){
    asm volatile("ldmatrix.sync.aligned.m8n8.x4.shared.b16 {%0,%1,%2,%3}, [%4];"
        : "=r"(r[0]), "=r"(r[1]), "=r"(r[2]), "=r"(r[3]) : "r"(a));
}
__device__ __forceinline__ void mma_bf16(float* c, const uint32_t* a, const uint32_t* b){
    asm volatile("mma.sync.aligned.m16n8k16.row.col.f32.bf16.bf16.f32 "
        "{%0,%1,%2,%3}, {%4,%5,%6,%7}, {%8,%9}, {%0,%1,%2,%3};"
        : "+f"(c[0]), "+f"(c[1]), "+f"(c[2]), "+f"(c[3])
        : "r"(a[0]), "r"(a[1]), "r"(a[2]), "r"(a[3]), "r"(b[0]), "r"(b[1]));
}

// ---------------- HMMA GEMM: C[M,N] = Ah*Bh + Ah*Bl + Al*Bh (+bias)(+add) ----
// A: [M,K] bf16 row-major (hi/lo). B: [N,K] bf16 row-major (hi/lo).
// 128x128 CTA tile, BK=32, 4 cp.async stages, 256 threads (8 warps, 4x2 MxN).
#define GBK 32
#define STAGES 4
#define TILEB (128*32*2)           // 8192 B per bf16 tile
#define STGB (4*TILEB)             // 32768 B per stage (Ahi,Alo,Bhi,Blo)
#define GEMM_SMEM (STAGES*STGB)    // 131072

__global__ __launch_bounds__(256, 1)
void tc_gemm(const __nv_bfloat16* __restrict__ Ahi, const __nv_bfloat16* __restrict__ Alo,
             const __nv_bfloat16* __restrict__ Bhi, const __nv_bfloat16* __restrict__ Blo,
             const float* __restrict__ bias, const float* __restrict__ add,
             float* __restrict__ C, int K, int ldc)
{
    extern __shared__ __align__(1024) char smem[];
    uint32_t sb = smem_u32(smem);
    int tid = threadIdx.x, wid = tid >> 5, lane = tid & 31;
    int m0 = blockIdx.y * 128, n0 = blockIdx.x * 128;
    int warp_m = wid & 3, warp_n = wid >> 2;   // 4 x 2 warps -> 32 x 64 per warp

    const int KT = K / GBK;

    auto issue_loads = [&](int s, int kt){
        int k0 = kt * GBK;
        uint32_t stg = sb + s * STGB;
        #pragma unroll
        for (int t = 0; t < 4; t++) {
            const __nv_bfloat16* src = (t == 0 ? Ahi : t == 1 ? Alo : t == 2 ? Bhi : Blo);
            int rb = (t < 2 ? m0 : n0);
            #pragma unroll
            for (int i = 0; i < 2; i++) {
                int id = i * 256 + tid;
                int r = id >> 2, c = id & 3;          // row 0..127, 16B chunk 0..3
                const void* g = src + (size_t)(rb + r) * K + k0 + c * 8;
                uint32_t off = (uint32_t)(r * 64 + c * 16);
                uint32_t d = stg + t * TILEB + SWZ64(off);
                asm volatile("cp.async.cg.shared.global [%0], [%1], 16;\n" :: "r"(d), "l"(g));
            }
        }
        asm volatile("cp.async.commit_group;\n" ::: "memory");
    };

    float acc[2][8][4];
    #pragma unroll
    for (int mt = 0; mt < 2; mt++)
        #pragma unroll
        for (int nt = 0; nt < 8; nt++)
            #pragma unroll
            for (int i = 0; i < 4; i++) acc[mt][nt][i] = 0.0f;

    issue_loads(0, 0);
    issue_loads(1, 1);
    issue_loads(2, 2);

    for (int kt = 0; kt < KT; kt++) {
        asm volatile("cp.async.wait_group 2;\n" ::: "memory");
        __syncthreads();
        if (kt + 3 < KT) issue_loads((kt + 3) % STAGES, kt + 3);

        uint32_t stg = sb + (kt % STAGES) * STGB;
        #pragma unroll
        for (int kk = 0; kk < 2; kk++) {
            uint32_t a_h[2][4], a_l[2][4];
            #pragma unroll
            for (int mt = 0; mt < 2; mt++) {
                int row = warp_m * 32 + mt * 16 + (lane & 15);
                uint32_t off = (uint32_t)(row * 64 + kk * 32 + (lane >> 4) * 16);
                uint32_t sw = SWZ64(off);
                ldsm_x4(a_h[mt], stg + sw);
                ldsm_x4(a_l[mt], stg + TILEB + sw);
            }
            uint32_t b_h[8][2], b_l[8][2];
            #pragma unroll
            for (int np = 0; np < 4; np++) {
                int nrow = warp_n * 64 + np * 16 + (lane & 7) + ((lane >> 4) << 3);
                uint32_t off = (uint32_t)(nrow * 64 + kk * 32 + ((lane >> 3) & 1) * 16);
                uint32_t sw = SWZ64(off);
                uint32_t t4[4];
                ldsm_x4(t4, stg + 2 * TILEB + sw);
                b_h[2*np][0] = t4[0]; b_h[2*np][1] = t4[1];
                b_h[2*np+1][0] = t4[2]; b_h[2*np+1][1] = t4[3];
                ldsm_x4(t4, stg + 3 * TILEB + sw);
                b_l[2*np][0] = t4[0]; b_l[2*np][1] = t4[1];
                b_l[2*np+1][0] = t4[2]; b_l[2*np+1][1] = t4[3];
            }
            #pragma unroll
            for (int mt = 0; mt < 2; mt++)
                #pragma unroll
                for (int nt = 0; nt < 8; nt++) {
                    mma_bf16(acc[mt][nt], a_h[mt], b_h[nt]);
                    mma_bf16(acc[mt][nt], a_h[mt], b_l[nt]);
                    mma_bf16(acc[mt][nt], a_l[mt], b_h[nt]);
                }
        }
        __syncthreads();
    }

    // epilogue: direct register -> gmem
    #pragma unroll
    for (int mt = 0; mt < 2; mt++) {
        #pragma unroll
        for (int half = 0; half < 2; half++) {
            int r = m0 + warp_m * 32 + mt * 16 + (lane >> 2) + half * 8;
            size_t crow = (size_t)r * ldc;
            #pragma unroll
            for (int nt = 0; nt < 8; nt++) {
                int c = n0 + warp_n * 64 + nt * 8 + (lane & 3) * 2;
                float2 v;
                v.x = acc[mt][nt][half * 2 + 0];
                v.y = acc[mt][nt][half * 2 + 1];
                if (bias) { v.x += bias[c]; v.y += bias[c + 1]; }
                if (add) {
                    float2 a = *(const float2*)&add[crow + c];
                    v.x += a.x; v.y += a.y;
                }
                *(float2*)&C[crow + c] = v;
            }
        }
    }
}

// ---------------- RMSNorm fused with bf16 hi/lo split ----------------
__global__ __launch_bounds__(256)
void rmsnorm_split_kernel(const float* __restrict__ x, const float* __restrict__ w,
                          __nv_bfloat16* __restrict__ ohi, __nv_bfloat16* __restrict__ olo)
{
    int row = blockIdx.x;
    const float* xr = x + (size_t)row * DD;
    int t = threadIdx.x;

    float v0 = xr[t], v1 = xr[t + 256], v2 = xr[t + 512], v3 = xr[t + 768];
    float ss = v0*v0 + v1*v1 + v2*v2 + v3*v3;
    #pragma unroll
    for (int off = 16; off; off >>= 1) ss += __shfl_xor_sync(0xffffffffu, ss, off);
    __shared__ float red[8];
    int wid = t >> 5, lid = t & 31;
    if (lid == 0) red[wid] = ss;
    __syncthreads();
    float tot = red[0]+red[1]+red[2]+red[3]+red[4]+red[5]+red[6]+red[7];
    float inv = rsqrtf(tot * (1.0f / (float)DD) + 1e-6f);

    size_t base = (size_t)row * DD;
    #pragma unroll
    for (int i = 0; i < 4; i++) {
        int c = t + i * 256;
        float val = w[c] * (i==0?v0:i==1?v1:i==2?v2:v3) * inv;
        __nv_bfloat16 hi = __float2bfloat16(val);
        float lo = val - __bfloat162float(hi);
        ohi[base + c] = hi;
        olo[base + c] = __float2bfloat16(lo);
    }
}

// ---------------- weight transpose + split: dst[n][k] = split(src[k][n]) ----
__global__ __launch_bounds__(256)
void tsplit_kernel(const float* __restrict__ src, __nv_bfloat16* __restrict__ dhi,
                   __nv_bfloat16* __restrict__ dlo, int Ks, int Ns, int Kout)
{
    __shared__ float ts[32][33];
    int kt = blockIdx.x * 32, nt = blockIdx.y * 32;
    int tx = threadIdx.x & 31, ty = threadIdx.x >> 5;   // 32 x 8
    #pragma unroll
    for (int i = 0; i < 4; i++) {
        int k = kt + ty + 8 * i, n = nt + tx;
        ts[ty + 8 * i][tx] = (k < Ks && n < Ns) ? src[(size_t)k * Ns + n] : 0.0f;
    }
    __syncthreads();
    #pragma unroll
    for (int i = 0; i < 4; i++) {
        int n = nt + ty + 8 * i, k = kt + tx;
        float v = ts[tx][ty + 8 * i];
        __nv_bfloat16 hi = __float2bfloat16(v);
        float lo = v - __bfloat162float(hi);
        dhi[(size_t)n * Kout + k] = hi;
        dlo[(size_t)n * Kout + k] = __float2bfloat16(lo);
    }
}

__global__ __launch_bounds__(256)
void bias_concat_kernel(const float* __restrict__ bq, const float* __restrict__ bk,
                        const float* __restrict__ bv, float* __restrict__ dst)
{
    int i = blockIdx.x * 256 + threadIdx.x;
    if (i < 1024)       dst[i] = bq[i];
    else if (i < 2048)  dst[i] = bk[i - 1024];
    else if (i < 3072)  dst[i] = bv[i - 2048];
}

// ---------------- flash attention (fp32) reading fused qkv, writing hi/lo ----
#define AT_KT 32
__global__ __launch_bounds__(128)
void attn_kernel(const float* __restrict__ qkv, const unsigned char* __restrict__ kpm,
                 __nv_bfloat16* __restrict__ ohi, __nv_bfloat16* __restrict__ olo)
{
    int bh = blockIdx.y;
    int b = bh / HH, h = bh % HH;
    int qi = blockIdx.x * 128 + threadIdx.x;

    __shared__ float ks[AT_KT][HDD];
    __shared__ float vs[AT_KT][HDD];
    __shared__ unsigned char kpms[AT_KT];

    float qr[HDD];
    const float* qp = qkv + (size_t)(b * SS + qi) * QKVN + h * HDD;
    #pragma unroll
    for (int d = 0; d < HDD; d += 4) {
        float4 t = *(const float4*)(qp + d);
        qr[d] = t.x; qr[d+1] = t.y; qr[d+2] = t.z; qr[d+3] = t.w;
    }

    float slope = -exp2f(-0.5f * (float)(h + 1));
    float m = -INFINITY, l = 0.0f;
    float o[HDD];
    #pragma unroll
    for (int d = 0; d < HDD; d++) o[d] = 0.0f;

    int qmax = blockIdx.x * 128 + 127;
    int ntiles = qmax / AT_KT + 1;

    for (int t = 0; t < ntiles; t++) {
        int j0 = t * AT_KT;
        __syncthreads();
        for (int i = threadIdx.x; i < AT_KT * (HDD / 4); i += 128) {
            int row = i / (HDD / 4);
            int c4  = i % (HDD / 4);
            size_t base = (size_t)(b * SS + j0 + row) * QKVN + h * HDD + c4 * 4;
            ((float4*)ks[row])[c4] = *(const float4*)(qkv + base + 1024);
            ((float4*)vs[row])[c4] = *(const float4*)(qkv + base + 2048);
        }
        if (threadIdx.x < AT_KT)
            kpms[threadIdx.x] = kpm[b * SS + j0 + threadIdx.x];
        __syncthreads();

        float s[AT_KT];
        float tmax = -INFINITY;
        #pragma unroll
        for (int j = 0; j < AT_KT; j++) {
            int jj = j0 + j;
            float acc = 0.0f;
            #pragma unroll
            for (int d4 = 0; d4 < HDD / 4; d4++) {
                float4 kv = ((const float4*)ks[j])[d4];
                acc += qr[d4*4+0] * kv.x;
                acc += qr[d4*4+1] * kv.y;
                acc += qr[d4*4+2] * kv.z;
                acc += qr[d4*4+3] * kv.w;
            }
            float sc = acc * 0.125f + slope * fabsf((float)(qi - jj));
            if (jj > qi || kpms[j]) sc = -INFINITY;
            s[j] = sc;
            tmax = fmaxf(tmax, sc);
        }
        if (tmax > -INFINITY) {
            float mnew = fmaxf(m, tmax);
            float corr = __expf(m - mnew);
            l *= corr;
            #pragma unroll
            for (int d = 0; d < HDD; d++) o[d] *= corr;
            m = mnew;
            #pragma unroll
            for (int j = 0; j < AT_KT; j++) {
                float p = __expf(s[j] - m);
                l += p;
                #pragma unroll
                for (int d4 = 0; d4 < HDD / 4; d4++) {
                    float4 vv = ((const float4*)vs[j])[d4];
                    o[d4*4+0] += p * vv.x;
                    o[d4*4+1] += p * vv.y;
                    o[d4*4+2] += p * vv.z;
                    o[d4*4+3] += p * vv.w;
                }
            }
        }
    }

    float inv = 1.0f / l;
    size_t ob = (size_t)(b * SS + qi) * DD + h * HDD;
    #pragma unroll
    for (int d = 0; d < HDD; d++) {
        float val = o[d] * inv;
        __nv_bfloat16 hi = __float2bfloat16(val);
        float lo = val - __bfloat162float(hi);
        ohi[ob + d] = hi;
        olo[ob + d] = __float2bfloat16(lo);
    }
}

// ---------------- SwiGLU with split + pad ----------------
__global__ __launch_bounds__(256)
void swiglu_split_kernel(const float* __restrict__ gu,
                         __nv_bfloat16* __restrict__ ahi, __nv_bfloat16* __restrict__ alo)
{
    size_t idx = (size_t)blockIdx.x * 256 + threadIdx.x;
    if (idx >= (size_t)MM * IPAD) return;
    int mrow = (int)(idx / IPAD);
    int i = (int)(idx % IPAD);
    float val = 0.0f;
    if (i < II) {
        float g = gu[(size_t)mrow * GUN + i];
        float u = gu[(size_t)mrow * GUN + IPAD + i];
        float sig = 1.0f / (1.0f + __expf(-g));
        val = g * sig * u;
    }
    __nv_bfloat16 hi = __float2bfloat16(val);
    float lo = val - __bfloat162float(hi);
    ahi[idx] = hi;
    alo[idx] = __float2bfloat16(lo);
}

// ---------------- launch ----------------
extern "C" void kernel_launch(void* const* d_in, const int* in_sizes, int n_in,
                              void* d_out, int out_size)
{
    const float* x      = (const float*)d_in[0];
    const float* wq     = (const float*)d_in[1];
    const float* bq     = (const float*)d_in[2];
    const float* wk     = (const float*)d_in[3];
    const float* bk     = (const float*)d_in[4];
    const float* wv     = (const float*)d_in[5];
    const float* bv     = (const float*)d_in[6];
    const float* wo     = (const float*)d_in[7];
    const float* bo     = (const float*)d_in[8];
    const float* w_gate = (const float*)d_in[9];
    const float* w_up   = (const float*)d_in[10];
    const float* w_down = (const float*)d_in[11];
    const float* ln1w   = (const float*)d_in[12];
    const float* ln2w   = (const float*)d_in[13];
    const unsigned char* kpm = (const unsigned char*)d_in[16];
    float* out = (float*)d_out;

    __nv_bfloat16 *h_hi, *h_lo, *attn_hi, *attn_lo, *h2_hi, *h2_lo, *act_hi, *act_lo;
    __nv_bfloat16 *wqkvT_hi, *wqkvT_lo, *woT_hi, *woT_lo, *wguT_hi, *wguT_lo, *wdT_hi, *wdT_lo;
    float *qkv, *res1, *gu, *bqkv;
    cudaGetSymbolAddress((void**)&h_hi, g_h_hi);     cudaGetSymbolAddress((void**)&h_lo, g_h_lo);
    cudaGetSymbolAddress((void**)&qkv, g_qkv);
    cudaGetSymbolAddress((void**)&attn_hi, g_attn_hi); cudaGetSymbolAddress((void**)&attn_lo, g_attn_lo);
    cudaGetSymbolAddress((void**)&res1, g_res1);
    cudaGetSymbolAddress((void**)&h2_hi, g_h2_hi);   cudaGetSymbolAddress((void**)&h2_lo, g_h2_lo);
    cudaGetSymbolAddress((void**)&gu, g_gu);
    cudaGetSymbolAddress((void**)&act_hi, g_act_hi); cudaGetSymbolAddress((void**)&act_lo, g_act_lo);
    cudaGetSymbolAddress((void**)&wqkvT_hi, g_wqkvT_hi); cudaGetSymbolAddress((void**)&wqkvT_lo, g_wqkvT_lo);
    cudaGetSymbolAddress((void**)&woT_hi, g_woT_hi); cudaGetSymbolAddress((void**)&woT_lo, g_woT_lo);
    cudaGetSymbolAddress((void**)&wguT_hi, g_wguT_hi); cudaGetSymbolAddress((void**)&wguT_lo, g_wguT_lo);
    cudaGetSymbolAddress((void**)&wdT_hi, g_wdT_hi); cudaGetSymbolAddress((void**)&wdT_lo, g_wdT_lo);
    cudaGetSymbolAddress((void**)&bqkv, g_bqkv);

    cudaFuncSetAttribute(tc_gemm, cudaFuncAttributeMaxDynamicSharedMemorySize, GEMM_SMEM);

    // weight prep
    tsplit_kernel<<<dim3(32, 32), 256>>>(wq, wqkvT_hi,                 wqkvT_lo,                 1024, 1024, 1024);
    tsplit_kernel<<<dim3(32, 32), 256>>>(wk, wqkvT_hi + 1024 * 1024,   wqkvT_lo + 1024 * 1024,   1024, 1024, 1024);
    tsplit_kernel<<<dim3(32, 32), 256>>>(wv, wqkvT_hi + 2048 * 1024,   wqkvT_lo + 2048 * 1024,   1024, 1024, 1024);
    tsplit_kernel<<<dim3(32, 32), 256>>>(wo, woT_hi, woT_lo, 1024, 1024, 1024);
    tsplit_kernel<<<dim3(32, 120), 256>>>(w_gate, wguT_hi,               wguT_lo,               1024, II, 1024);
    tsplit_kernel<<<dim3(32, 120), 256>>>(w_up,   wguT_hi + IPAD * 1024, wguT_lo + IPAD * 1024, 1024, II, 1024);
    tsplit_kernel<<<dim3(120, 32), 256>>>(w_down, wdT_hi, wdT_lo, II, 1024, IPAD);
    bias_concat_kernel<<<12, 256>>>(bq, bk, bv, bqkv);

    // 1) h = rmsnorm(x) -> hi/lo
    rmsnorm_split_kernel<<<MM, 256>>>(x, ln1w, h_hi, h_lo);
    // 2) qkv = h @ Wqkv^T + bqkv
    tc_gemm<<<dim3(QKVN / 128, MM / 128), 256, GEMM_SMEM>>>(h_hi, h_lo, wqkvT_hi, wqkvT_lo,
                                                            bqkv, nullptr, qkv, DD, QKVN);
    // 3) attention -> attn hi/lo
    attn_kernel<<<dim3(SS / 128, BB * HH), 128>>>(qkv, kpm, attn_hi, attn_lo);
    // 4) res1 = attn @ Wo^T + bo + x
    tc_gemm<<<dim3(DD / 128, MM / 128), 256, GEMM_SMEM>>>(attn_hi, attn_lo, woT_hi, woT_lo,
                                                          bo, x, res1, DD, DD);
    // 5) h2 = rmsnorm(res1) -> hi/lo
    rmsnorm_split_kernel<<<MM, 256>>>(res1, ln2w, h2_hi, h2_lo);
    // 6) gu = h2 @ [Wgate|Wup]^T
    tc_gemm<<<dim3(GUN / 128, MM / 128), 256, GEMM_SMEM>>>(h2_hi, h2_lo, wguT_hi, wguT_lo,
                                                           nullptr, nullptr, gu, DD, GUN);
    // 7) act = silu(gate)*up -> hi/lo (padded)
    {
        size_t n = (size_t)MM * IPAD;
        int blocks = (int)((n + 255) / 256);
        swiglu_split_kernel<<<blocks, 256>>>(gu, act_hi, act_lo);
    }
    // 8) out = act @ Wdown^T + res1
    tc_gemm<<<dim3(DD / 128, MM / 128), 256, GEMM_SMEM>>>(act_hi, act_lo, wdT_hi, wdT_lo,
                                                          nullptr, res1, out, IPAD, DD);

    (void)in_sizes; (void)n_in; (void)out_size;
}

// round 5
// speedup vs baseline: 3.1402x; 1.6464x over previous
#include <cuda_runtime.h>
#include <cuda_bf16.h>
#include <math.h>
#include <stdint.h>

// ---------------- problem dims ----------------
#define BB 2
#define SS 2048
#define DD 1024
#define HH 16
#define HDD 64
#define II 3752
#define MM (BB*SS)          // 4096
#define QKVN 3072
#define IPAD 3840
#define GUN (2*IPAD)        // 7680

// ---------------- scratch ----------------
__device__ __nv_bfloat16 g_h_hi[MM*DD],  g_h_lo[MM*DD];
__device__ __nv_bfloat16 g_qkv_hi[(size_t)MM*QKVN], g_qkv_lo[(size_t)MM*QKVN];
__device__ __nv_bfloat16 g_attn_hi[MM*DD], g_attn_lo[MM*DD];
__device__ float         g_res1[MM*DD];
__device__ __nv_bfloat16 g_h2_hi[MM*DD], g_h2_lo[MM*DD];
__device__ float         g_gu[(size_t)MM*GUN];
__device__ __nv_bfloat16 g_act_hi[(size_t)MM*IPAD], g_act_lo[(size_t)MM*IPAD];
__device__ __nv_bfloat16 g_wqkvT_hi[QKVN*DD], g_wqkvT_lo[QKVN*DD];
__device__ __nv_bfloat16 g_woT_hi[DD*DD],     g_woT_lo[DD*DD];
__device__ __nv_bfloat16 g_wguT_hi[GUN*DD],   g_wguT_lo[GUN*DD];
__device__ __nv_bfloat16 g_wdT_hi[DD*IPAD],   g_wdT_lo[DD*IPAD];
__device__ float         g_bqkv[QKVN];

// ---------------- helpers ----------------
__device__ __forceinline__ uint32_t smem_u32(const void* p){
    uint32_t r;
    asm("{ .reg .u64 t; cvta.to.shared.u64 t, %1; cvt.u32.u64 %0, t; }" : "=r"(r) : "l"(p));
    return r;
}
#define SWZ64(x)  ((x) ^ (((x) >> 3) & 0x30))
#define SWZ128(x) ((x) ^ (((x) >> 3) & 0x70))

__device__ __forceinline__ void ldsm_x4(uint32_t* r, uint32_t a){
    asm volatile("ldmatrix.sync.aligned.m8n8.x4.shared.b16 {%0,%1,%2,%3}, [%4];"
        : "=r"(r[0]), "=r"(r[1]), "=r"(r[2]), "=r"(r[3]) : "r"(a));
}
__device__ __forceinline__ void ldsm_x4_t(uint32_t* r, uint32_t a){
    asm volatile("ldmatrix.sync.aligned.m8n8.x4.trans.shared.b16 {%0,%1,%2,%3}, [%4];"
        : "=r"(r[0]), "=r"(r[1]), "=r"(r[2]), "=r"(r[3]) : "r"(a));
}
__device__ __forceinline__ void mma_bf16(float* c, const uint32_t* a, uint32_t b0, uint32_t b1){
    asm volatile("mma.sync.aligned.m16n8k16.row.col.f32.bf16.bf16.f32 "
        "{%0,%1,%2,%3}, {%4,%5,%6,%7}, {%8,%9}, {%0,%1,%2,%3};"
        : "+f"(c[0]), "+f"(c[1]), "+f"(c[2]), "+f"(c[3])
        : "r"(a[0]), "r"(a[1]), "r"(a[2]), "r"(a[3]), "r"(b0), "r"(b1));
}
__device__ __forceinline__ uint32_t pack_bf16(float lo_elem, float hi_elem){
    uint32_t r;
    asm("cvt.rn.bf16x2.f32 %0, %1, %2;" : "=r"(r) : "f"(hi_elem), "f"(lo_elem));
    return r;
}
#define CPA16(d, g) asm volatile("cp.async.cg.shared.global [%0], [%1], 16;\n" :: "r"(d), "l"(g))
#define CPA_COMMIT() asm volatile("cp.async.commit_group;\n" ::: "memory")

// ---------------- HMMA GEMM ----------------
// C = Ah*Bh + Ah*Bl + Al*Bh (+bias)(+add). A [M,K] rm hi/lo, B [N,K] rm hi/lo.
// If Ohi != null: write split bf16 hi/lo (cols < qscale_cols scaled by 0.125) instead of C.
#define GBK 32
#define STAGES 4
#define TILEB (128*32*2)
#define STGB (4*TILEB)
#define GEMM_SMEM (STAGES*STGB)

__global__ __launch_bounds__(256, 1)
void tc_gemm(const __nv_bfloat16* __restrict__ Ahi, const __nv_bfloat16* __restrict__ Alo,
             const __nv_bfloat16* __restrict__ Bhi, const __nv_bfloat16* __restrict__ Blo,
             const float* __restrict__ bias, const float* __restrict__ add,
             float* __restrict__ C, int K, int ldc,
             __nv_bfloat16* __restrict__ Ohi, __nv_bfloat16* __restrict__ Olo, int qscale_cols)
{
    extern __shared__ __align__(1024) char smem[];
    uint32_t sb = smem_u32(smem);
    int tid = threadIdx.x, wid = tid >> 5, lane = tid & 31;
    int m0 = blockIdx.y * 128, n0 = blockIdx.x * 128;
    int warp_m = wid & 3, warp_n = wid >> 2;

    const int KT = K / GBK;

    auto issue_loads = [&](int s, int kt){
        int k0 = kt * GBK;
        uint32_t stg = sb + s * STGB;
        #pragma unroll
        for (int t = 0; t < 4; t++) {
            const __nv_bfloat16* src = (t == 0 ? Ahi : t == 1 ? Alo : t == 2 ? Bhi : Blo);
            int rb = (t < 2 ? m0 : n0);
            #pragma unroll
            for (int i = 0; i < 2; i++) {
                int id = i * 256 + tid;
                int r = id >> 2, c = id & 3;
                const void* g = src + (size_t)(rb + r) * K + k0 + c * 8;
                uint32_t d = stg + t * TILEB + SWZ64((uint32_t)(r * 64 + c * 16));
                CPA16(d, g);
            }
        }
        CPA_COMMIT();
    };

    float acc[2][8][4];
    #pragma unroll
    for (int mt = 0; mt < 2; mt++)
        #pragma unroll
        for (int nt = 0; nt < 8; nt++)
            #pragma unroll
            for (int i = 0; i < 4; i++) acc[mt][nt][i] = 0.0f;

    issue_loads(0, 0);
    issue_loads(1, 1);
    issue_loads(2, 2);

    for (int kt = 0; kt < KT; kt++) {
        asm volatile("cp.async.wait_group 2;\n" ::: "memory");
        __syncthreads();
        if (kt + 3 < KT) issue_loads((kt + 3) % STAGES, kt + 3);

        uint32_t stg = sb + (kt % STAGES) * STGB;
        #pragma unroll
        for (int kk = 0; kk < 2; kk++) {
            uint32_t a_h[2][4], a_l[2][4];
            #pragma unroll
            for (int mt = 0; mt < 2; mt++) {
                int row = warp_m * 32 + mt * 16 + (lane & 15);
                uint32_t sw = SWZ64((uint32_t)(row * 64 + kk * 32 + (lane >> 4) * 16));
                ldsm_x4(a_h[mt], stg + sw);
                ldsm_x4(a_l[mt], stg + TILEB + sw);
            }
            uint32_t b_h[8][2], b_l[8][2];
            #pragma unroll
            for (int np = 0; np < 4; np++) {
                int nrow = warp_n * 64 + np * 16 + (lane & 7) + ((lane >> 4) << 3);
                uint32_t sw = SWZ64((uint32_t)(nrow * 64 + kk * 32 + ((lane >> 3) & 1) * 16));
                uint32_t t4[4];
                ldsm_x4(t4, stg + 2 * TILEB + sw);
                b_h[2*np][0] = t4[0]; b_h[2*np][1] = t4[1];
                b_h[2*np+1][0] = t4[2]; b_h[2*np+1][1] = t4[3];
                ldsm_x4(t4, stg + 3 * TILEB + sw);
                b_l[2*np][0] = t4[0]; b_l[2*np][1] = t4[1];
                b_l[2*np+1][0] = t4[2]; b_l[2*np+1][1] = t4[3];
            }
            #pragma unroll
            for (int mt = 0; mt < 2; mt++)
                #pragma unroll
                for (int nt = 0; nt < 8; nt++) {
                    mma_bf16(acc[mt][nt], a_h[mt], b_h[nt][0], b_h[nt][1]);
                    mma_bf16(acc[mt][nt], a_h[mt], b_l[nt][0], b_l[nt][1]);
                    mma_bf16(acc[mt][nt], a_l[mt], b_h[nt][0], b_h[nt][1]);
                }
        }
        __syncthreads();
    }

    #pragma unroll
    for (int mt = 0; mt < 2; mt++) {
        #pragma unroll
        for (int half = 0; half < 2; half++) {
            int r = m0 + warp_m * 32 + mt * 16 + (lane >> 2) + half * 8;
            size_t crow = (size_t)r * ldc;
            #pragma unroll
            for (int nt = 0; nt < 8; nt++) {
                int c = n0 + warp_n * 64 + nt * 8 + (lane & 3) * 2;
                float2 v;
                v.x = acc[mt][nt][half * 2 + 0];
                v.y = acc[mt][nt][half * 2 + 1];
                if (bias) { v.x += bias[c]; v.y += bias[c + 1]; }
                if (add) {
                    float2 a = *(const float2*)&add[crow + c];
                    v.x += a.x; v.y += a.y;
                }
                if (Ohi) {
                    if (c < qscale_cols) { v.x *= 0.125f; v.y *= 0.125f; }
                    __nv_bfloat16 hx = __float2bfloat16(v.x);
                    __nv_bfloat16 hy = __float2bfloat16(v.y);
                    float lx = v.x - __bfloat162float(hx);
                    float ly = v.y - __bfloat162float(hy);
                    *(uint32_t*)&Ohi[crow + c] = pack_bf16(v.x, v.y); // rn-packed hi pair
                    // note: pack_bf16 rounds; recompute lo against packed his
                    (void)hx; (void)hy;
                    __nv_bfloat16* hp = (__nv_bfloat16*)&Ohi[crow + c];
                    lx = v.x - __bfloat162float(hp[0]);
                    ly = v.y - __bfloat162float(hp[1]);
                    *(uint32_t*)&Olo[crow + c] = pack_bf16(lx, ly);
                } else {
                    *(float2*)&C[crow + c] = v;
                }
            }
        }
    }
}

// ---------------- FA2-style HMMA attention ----------------
// grid (S/128, B*H), 256 threads (8 warps x m16). 64-key tiles, 2 stages.
#define AQ 128
#define AK 64
#define SM_QHI 0
#define SM_QLO 16384
#define SM_KV  32768
#define SO_KHI 0
#define SO_KLO 8192
#define SO_VHI 16384
#define SO_VLO 24576
#define KV_STG 32768
#define SM_KPM (SM_KV + 2*KV_STG)     // 98304
#define ATTN_SMEM (SM_KPM + 128)      // 98432

__global__ __launch_bounds__(256, 1)
void attn_mma_kernel(const __nv_bfloat16* __restrict__ qkv_hi,
                     const __nv_bfloat16* __restrict__ qkv_lo,
                     const unsigned char* __restrict__ kpm,
                     __nv_bfloat16* __restrict__ ohi, __nv_bfloat16* __restrict__ olo)
{
    extern __shared__ __align__(1024) char smem[];
    uint32_t sb = smem_u32(smem);
    int tid = threadIdx.x, wid = tid >> 5, lane = tid & 31;
    int qt = blockIdx.x, bh = blockIdx.y;
    int b = bh >> 4, h = bh & 15;
    size_t row0 = (size_t)(b * SS + qt * AQ);

    auto issue_kv = [&](int t){
        int s = t & 1;
        int j0 = t * AK;
        uint32_t stg = sb + SM_KV + s * KV_STG;
        #pragma unroll
        for (int i = 0; i < 2; i++) {
            int id = i * 256 + tid;       // 0..511
            int r = id >> 3, c = id & 7;
            size_t g = (size_t)(b * SS + j0 + r) * QKVN + h * HDD + c * 8;
            uint32_t sw = SWZ128((uint32_t)(r * 128 + c * 16));
            CPA16(stg + SO_KHI + sw, qkv_hi + g + 1024);
            CPA16(stg + SO_KLO + sw, qkv_lo + g + 1024);
            CPA16(stg + SO_VHI + sw, qkv_hi + g + 2048);
            CPA16(stg + SO_VLO + sw, qkv_lo + g + 2048);
        }
        if (tid < 4)
            CPA16(sb + SM_KPM + s * 64 + tid * 16, kpm + (size_t)b * SS + j0 + tid * 16);
        CPA_COMMIT();
    };

    const int T = 2 * qt + 2;

    issue_kv(0);
    // Q tile (group)
    #pragma unroll
    for (int i = 0; i < 4; i++) {
        int id = i * 256 + tid;           // 0..1023
        int r = id >> 3, c = id & 7;
        size_t g = (row0 + r) * QKVN + h * HDD + c * 8;
        uint32_t sw = SWZ128((uint32_t)(r * 128 + c * 16));
        CPA16(sb + SM_QHI + sw, qkv_hi + g);
        CPA16(sb + SM_QLO + sw, qkv_lo + g);
    }
    CPA_COMMIT();
    issue_kv(1);

    asm volatile("cp.async.wait_group 1;\n" ::: "memory");
    __syncthreads();

    // Q fragments (persist in regs)
    uint32_t qh[4][4], ql[4][4];
    {
        int row = wid * 16 + (lane & 15);
        #pragma unroll
        for (int kk = 0; kk < 4; kk++) {
            uint32_t sw = SWZ128((uint32_t)(row * 128 + kk * 32 + (lane >> 4) * 16));
            ldsm_x4(qh[kk], sb + SM_QHI + sw);
            ldsm_x4(ql[kk], sb + SM_QLO + sw);
        }
    }

    float slope = -exp2f(-0.5f * (float)(h + 1));
    float m[2] = {-1e30f, -1e30f}, l[2] = {0.0f, 0.0f};
    float o[8][4];
    #pragma unroll
    for (int nt = 0; nt < 8; nt++)
        #pragma unroll
        for (int i = 0; i < 4; i++) o[nt][i] = 0.0f;

    int r0 = wid * 16 + (lane >> 2);

    for (int t = 0; t < T; t++) {
        if (t > 0) {
            asm volatile("cp.async.wait_group 1;\n" ::: "memory");
            __syncthreads();
        }
        uint32_t stg = sb + SM_KV + (t & 1) * KV_STG;
        const unsigned char* kpms = (const unsigned char*)(smem + SM_KPM + (t & 1) * 64);
        int j0 = t * AK;
        bool diag = (t >= 2 * qt);

        // ---- scores ----
        float s[8][4];
        #pragma unroll
        for (int nt = 0; nt < 8; nt++)
            #pragma unroll
            for (int i = 0; i < 4; i++) s[nt][i] = 0.0f;

        #pragma unroll
        for (int kk = 0; kk < 4; kk++) {
            #pragma unroll
            for (int np = 0; np < 4; np++) {
                int nrow = np * 16 + (lane & 7) + ((lane >> 4) << 3);
                uint32_t sw = SWZ128((uint32_t)(nrow * 128 + kk * 32 + ((lane >> 3) & 1) * 16));
                uint32_t bhh[4], bll[4];
                ldsm_x4(bhh, stg + SO_KHI + sw);
                ldsm_x4(bll, stg + SO_KLO + sw);
                mma_bf16(s[2*np],   qh[kk], bhh[0], bhh[1]);
                mma_bf16(s[2*np],   qh[kk], bll[0], bll[1]);
                mma_bf16(s[2*np],   ql[kk], bhh[0], bhh[1]);
                mma_bf16(s[2*np+1], qh[kk], bhh[2], bhh[3]);
                mma_bf16(s[2*np+1], qh[kk], bll[2], bll[3]);
                mma_bf16(s[2*np+1], ql[kk], bhh[2], bhh[3]);
            }
        }

        // ---- bias + mask + row max ----
        float mt[2] = {-1e30f, -1e30f};
        #pragma unroll
        for (int nt = 0; nt < 8; nt++) {
            #pragma unroll
            for (int i = 0; i < 4; i++) {
                int half = i >> 1;
                int qi = qt * AQ + r0 + half * 8;
                int jj = j0 + nt * 8 + (lane & 3) * 2 + (i & 1);
                float sc = s[nt][i] + slope * fabsf((float)(qi - jj));
                if ((diag && jj > qi) || kpms[jj - j0]) sc = -1e30f;
                s[nt][i] = sc;
                mt[half] = fmaxf(mt[half], sc);
            }
        }
        #pragma unroll
        for (int half = 0; half < 2; half++) {
            mt[half] = fmaxf(mt[half], __shfl_xor_sync(0xffffffffu, mt[half], 1));
            mt[half] = fmaxf(mt[half], __shfl_xor_sync(0xffffffffu, mt[half], 2));
            float mnew = fmaxf(m[half], mt[half]);
            float corr = __expf(m[half] - mnew);
            m[half] = mnew;
            l[half] *= corr;
            #pragma unroll
            for (int nt = 0; nt < 8; nt++) {
                o[nt][half*2 + 0] *= corr;
                o[nt][half*2 + 1] *= corr;
            }
        }
        // ---- p = exp(s - m) ----
        #pragma unroll
        for (int nt = 0; nt < 8; nt++) {
            #pragma unroll
            for (int i = 0; i < 4; i++) {
                float p = __expf(s[nt][i] - m[i >> 1]);
                s[nt][i] = p;
                l[i >> 1] += p;
            }
        }

        // ---- o += P @ V ----
        #pragma unroll
        for (int kc = 0; kc < 4; kc++) {
            uint32_t ph[4], pl[4];
            #pragma unroll
            for (int idx = 0; idx < 4; idx++) {
                int nt = 2 * kc + (idx >> 1);
                int ci = (idx & 1) * 2;
                float v0 = s[nt][ci], v1 = s[nt][ci + 1];
                ph[idx] = pack_bf16(v0, v1);
                __nv_bfloat16* hp = (__nv_bfloat16*)&ph[idx];
                pl[idx] = pack_bf16(v0 - __bfloat162float(hp[0]),
                                    v1 - __bfloat162float(hp[1]));
            }
            #pragma unroll
            for (int np = 0; np < 4; np++) {
                uint32_t sw = SWZ128((uint32_t)((kc * 16 + (lane & 15)) * 128 + np * 32 + (lane >> 4) * 16));
                uint32_t vh[4], vl[4];
                ldsm_x4_t(vh, stg + SO_VHI + sw);
                ldsm_x4_t(vl, stg + SO_VLO + sw);
                mma_bf16(o[2*np],   ph, vh[0], vh[1]);
                mma_bf16(o[2*np],   ph, vl[0], vl[1]);
                mma_bf16(o[2*np],   pl, vh[0], vh[1]);
                mma_bf16(o[2*np+1], ph, vh[2], vh[3]);
                mma_bf16(o[2*np+1], ph, vl[2], vl[3]);
                mma_bf16(o[2*np+1], pl, vh[2], vh[3]);
            }
        }

        __syncthreads();
        if (t + 2 < T) issue_kv(t + 2);
    }

    // ---- finalize ----
    float inv[2];
    #pragma unroll
    for (int half = 0; half < 2; half++) {
        float ls = l[half];
        ls += __shfl_xor_sync(0xffffffffu, ls, 1);
        ls += __shfl_xor_sync(0xffffffffu, ls, 2);
        inv[half] = 1.0f / ls;
    }
    #pragma unroll
    for (int nt = 0; nt < 8; nt++) {
        #pragma unroll
        for (int half = 0; half < 2; half++) {
            int row = qt * AQ + wid * 16 + (lane >> 2) + half * 8;
            int col = h * HDD + nt * 8 + (lane & 3) * 2;
            size_t off = (size_t)(b * SS + row) * DD + col;
            float v0 = o[nt][half*2 + 0] * inv[half];
            float v1 = o[nt][half*2 + 1] * inv[half];
            uint32_t hp = pack_bf16(v0, v1);
            *(uint32_t*)&ohi[off] = hp;
            __nv_bfloat16* hb = (__nv_bfloat16*)&hp;
            *(uint32_t*)&olo[off] = pack_bf16(v0 - __bfloat162float(hb[0]),
                                              v1 - __bfloat162float(hb[1]));
        }
    }
}

// ---------------- RMSNorm + split ----------------
__global__ __launch_bounds__(256)
void rmsnorm_split_kernel(const float* __restrict__ x, const float* __restrict__ w,
                          __nv_bfloat16* __restrict__ ohi, __nv_bfloat16* __restrict__ olo)
{
    int row = blockIdx.x;
    const float* xr = x + (size_t)row * DD;
    int t = threadIdx.x;

    float v0 = xr[t], v1 = xr[t + 256], v2 = xr[t + 512], v3 = xr[t + 768];
    float ss = v0*v0 + v1*v1 + v2*v2 + v3*v3;
    #pragma unroll
    for (int off = 16; off; off >>= 1) ss += __shfl_xor_sync(0xffffffffu, ss, off);
    __shared__ float red[8];
    int wid = t >> 5, lid = t & 31;
    if (lid == 0) red[wid] = ss;
    __syncthreads();
    float tot = red[0]+red[1]+red[2]+red[3]+red[4]+red[5]+red[6]+red[7];
    float inv = rsqrtf(tot * (1.0f / (float)DD) + 1e-6f);

    size_t base = (size_t)row * DD;
    #pragma unroll
    for (int i = 0; i < 4; i++) {
        int c = t + i * 256;
        float val = w[c] * (i==0?v0:i==1?v1:i==2?v2:v3) * inv;
        __nv_bfloat16 hi = __float2bfloat16(val);
        ohi[base + c] = hi;
        olo[base + c] = __float2bfloat16(val - __bfloat162float(hi));
    }
}

// ---------------- weight transpose + split ----------------
__global__ __launch_bounds__(256)
void tsplit_kernel(const float* __restrict__ src, __nv_bfloat16* __restrict__ dhi,
                   __nv_bfloat16* __restrict__ dlo, int Ks, int Ns, int Kout)
{
    __shared__ float ts[32][33];
    int kt = blockIdx.x * 32, nt = blockIdx.y * 32;
    int tx = threadIdx.x & 31, ty = threadIdx.x >> 5;
    #pragma unroll
    for (int i = 0; i < 4; i++) {
        int k = kt + ty + 8 * i, n = nt + tx;
        ts[ty + 8 * i][tx] = (k < Ks && n < Ns) ? src[(size_t)k * Ns + n] : 0.0f;
    }
    __syncthreads();
    #pragma unroll
    for (int i = 0; i < 4; i++) {
        int n = nt + ty + 8 * i, k = kt + tx;
        float v = ts[tx][ty + 8 * i];
        __nv_bfloat16 hi = __float2bfloat16(v);
        dhi[(size_t)n * Kout + k] = hi;
        dlo[(size_t)n * Kout + k] = __float2bfloat16(v - __bfloat162float(hi));
    }
}

__global__ __launch_bounds__(256)
void bias_concat_kernel(const float* __restrict__ bq, const float* __restrict__ bk,
                        const float* __restrict__ bv, float* __restrict__ dst)
{
    int i = blockIdx.x * 256 + threadIdx.x;
    if (i < 1024)       dst[i] = bq[i];
    else if (i < 2048)  dst[i] = bk[i - 1024];
    else if (i < 3072)  dst[i] = bv[i - 2048];
}

// ---------------- SwiGLU with split + pad ----------------
__global__ __launch_bounds__(256)
void swiglu_split_kernel(const float* __restrict__ gu,
                         __nv_bfloat16* __restrict__ ahi, __nv_bfloat16* __restrict__ alo)
{
    size_t idx = (size_t)blockIdx.x * 256 + threadIdx.x;
    if (idx >= (size_t)MM * IPAD) return;
    int mrow = (int)(idx / IPAD);
    int i = (int)(idx % IPAD);
    float val = 0.0f;
    if (i < II) {
        float g = gu[(size_t)mrow * GUN + i];
        float u = gu[(size_t)mrow * GUN + IPAD + i];
        float sig = 1.0f / (1.0f + __expf(-g));
        val = g * sig * u;
    }
    __nv_bfloat16 hi = __float2bfloat16(val);
    ahi[idx] = hi;
    alo[idx] = __float2bfloat16(val - __bfloat162float(hi));
}

// ---------------- launch ----------------
extern "C" void kernel_launch(void* const* d_in, const int* in_sizes, int n_in,
                              void* d_out, int out_size)
{
    const float* x      = (const float*)d_in[0];
    const float* wq     = (const float*)d_in[1];
    const float* bq     = (const float*)d_in[2];
    const float* wk     = (const float*)d_in[3];
    const float* bk     = (const float*)d_in[4];
    const float* wv     = (const float*)d_in[5];
    const float* bv     = (const float*)d_in[6];
    const float* wo     = (const float*)d_in[7];
    const float* bo     = (const float*)d_in[8];
    const float* w_gate = (const float*)d_in[9];
    const float* w_up   = (const float*)d_in[10];
    const float* w_down = (const float*)d_in[11];
    const float* ln1w   = (const float*)d_in[12];
    const float* ln2w   = (const float*)d_in[13];
    const unsigned char* kpm = (const unsigned char*)d_in[16];
    float* out = (float*)d_out;

    __nv_bfloat16 *h_hi, *h_lo, *qkv_hi, *qkv_lo, *attn_hi, *attn_lo, *h2_hi, *h2_lo, *act_hi, *act_lo;
    __nv_bfloat16 *wqkvT_hi, *wqkvT_lo, *woT_hi, *woT_lo, *wguT_hi, *wguT_lo, *wdT_hi, *wdT_lo;
    float *res1, *gu, *bqkv;
    cudaGetSymbolAddress((void**)&h_hi, g_h_hi);     cudaGetSymbolAddress((void**)&h_lo, g_h_lo);
    cudaGetSymbolAddress((void**)&qkv_hi, g_qkv_hi); cudaGetSymbolAddress((void**)&qkv_lo, g_qkv_lo);
    cudaGetSymbolAddress((void**)&attn_hi, g_attn_hi); cudaGetSymbolAddress((void**)&attn_lo, g_attn_lo);
    cudaGetSymbolAddress((void**)&res1, g_res1);
    cudaGetSymbolAddress((void**)&h2_hi, g_h2_hi);   cudaGetSymbolAddress((void**)&h2_lo, g_h2_lo);
    cudaGetSymbolAddress((void**)&gu, g_gu);
    cudaGetSymbolAddress((void**)&act_hi, g_act_hi); cudaGetSymbolAddress((void**)&act_lo, g_act_lo);
    cudaGetSymbolAddress((void**)&wqkvT_hi, g_wqkvT_hi); cudaGetSymbolAddress((void**)&wqkvT_lo, g_wqkvT_lo);
    cudaGetSymbolAddress((void**)&woT_hi, g_woT_hi); cudaGetSymbolAddress((void**)&woT_lo, g_woT_lo);
    cudaGetSymbolAddress((void**)&wguT_hi, g_wguT_hi); cudaGetSymbolAddress((void**)&wguT_lo, g_wguT_lo);
    cudaGetSymbolAddress((void**)&wdT_hi, g_wdT_hi); cudaGetSymbolAddress((void**)&wdT_lo, g_wdT_lo);
    cudaGetSymbolAddress((void**)&bqkv, g_bqkv);

    cudaFuncSetAttribute(tc_gemm, cudaFuncAttributeMaxDynamicSharedMemorySize, GEMM_SMEM);
    cudaFuncSetAttribute(attn_mma_kernel, cudaFuncAttributeMaxDynamicSharedMemorySize, ATTN_SMEM);

    // weight prep
    tsplit_kernel<<<dim3(32, 32), 256>>>(wq, wqkvT_hi,               wqkvT_lo,               1024, 1024, 1024);
    tsplit_kernel<<<dim3(32, 32), 256>>>(wk, wqkvT_hi + 1024 * 1024, wqkvT_lo + 1024 * 1024, 1024, 1024, 1024);
    tsplit_kernel<<<dim3(32, 32), 256>>>(wv, wqkvT_hi + 2048 * 1024, wqkvT_lo + 2048 * 1024, 1024, 1024, 1024);
    tsplit_kernel<<<dim3(32, 32), 256>>>(wo, woT_hi, woT_lo, 1024, 1024, 1024);
    tsplit_kernel<<<dim3(32, 120), 256>>>(w_gate, wguT_hi,               wguT_lo,               1024, II, 1024);
    tsplit_kernel<<<dim3(32, 120), 256>>>(w_up,   wguT_hi + IPAD * 1024, wguT_lo + IPAD * 1024, 1024, II, 1024);
    tsplit_kernel<<<dim3(120, 32), 256>>>(w_down, wdT_hi, wdT_lo, II, 1024, IPAD);
    bias_concat_kernel<<<12, 256>>>(bq, bk, bv, bqkv);

    // 1) h = rmsnorm(x) -> hi/lo
    rmsnorm_split_kernel<<<MM, 256>>>(x, ln1w, h_hi, h_lo);
    // 2) qkv = h @ Wqkv^T + bqkv -> bf16 hi/lo (q pre-scaled by 0.125)
    tc_gemm<<<dim3(QKVN / 128, MM / 128), 256, GEMM_SMEM>>>(h_hi, h_lo, wqkvT_hi, wqkvT_lo,
        bqkv, nullptr, nullptr, DD, QKVN, qkv_hi, qkv_lo, 1024);
    // 3) attention (HMMA) -> attn hi/lo
    attn_mma_kernel<<<dim3(SS / AQ, BB * HH), 256, ATTN_SMEM>>>(qkv_hi, qkv_lo, kpm, attn_hi, attn_lo);
    // 4) res1 = attn @ Wo^T + bo + x
    tc_gemm<<<dim3(DD / 128, MM / 128), 256, GEMM_SMEM>>>(attn_hi, attn_lo, woT_hi, woT_lo,
        bo, x, res1, DD, DD, nullptr, nullptr, 0);
    // 5) h2 = rmsnorm(res1) -> hi/lo
    rmsnorm_split_kernel<<<MM, 256>>>(res1, ln2w, h2_hi, h2_lo);
    // 6) gu = h2 @ [Wgate|Wup]^T
    tc_gemm<<<dim3(GUN / 128, MM / 128), 256, GEMM_SMEM>>>(h2_hi, h2_lo, wguT_hi, wguT_lo,
        nullptr, nullptr, gu, DD, GUN, nullptr, nullptr, 0);
    // 7) act = silu(gate)*up -> hi/lo (padded)
    {
        size_t n = (size_t)MM * IPAD;
        int blocks = (int)((n + 255) / 256);
        swiglu_split_kernel<<<blocks, 256>>>(gu, act_hi, act_lo);
    }
    // 8) out = act @ Wdown^T + res1
    tc_gemm<<<dim3(DD / 128, MM / 128), 256, GEMM_SMEM>>>(act_hi, act_lo, wdT_hi, wdT_lo,
        nullptr, res1, out, IPAD, DD, nullptr, nullptr, 0);

    (void)in_sizes; (void)n_in; (void)out_size;
}

// round 8
// speedup vs baseline: 3.2823x; 1.0453x over previous
#include <cuda_runtime.h>
#include <cuda_bf16.h>
#include <math.h>
#include <stdint.h>

// ---------------- problem dims ----------------
#define BB 2
#define SS 2048
#define DD 1024
#define HH 16
#define HDD 64
#define II 3752
#define MM (BB*SS)          // 4096
#define QKVN 3072
#define IPAD 3840
#define GUN (2*IPAD)        // 7680

// ---------------- scratch ----------------
__device__ __nv_bfloat16 g_h_hi[MM*DD],  g_h_lo[MM*DD];
__device__ __nv_bfloat16 g_qkv_hi[(size_t)MM*QKVN], g_qkv_lo[(size_t)MM*QKVN];
__device__ __nv_bfloat16 g_attn_hi[MM*DD], g_attn_lo[MM*DD];
__device__ float         g_res1[MM*DD];
__device__ __nv_bfloat16 g_h2_hi[MM*DD], g_h2_lo[MM*DD];
__device__ __nv_bfloat16 g_act_hi[(size_t)MM*IPAD], g_act_lo[(size_t)MM*IPAD];
__device__ __nv_bfloat16 g_wqkvT_hi[QKVN*DD], g_wqkvT_lo[QKVN*DD];
__device__ __nv_bfloat16 g_woT_hi[DD*DD],     g_woT_lo[DD*DD];
__device__ __nv_bfloat16 g_wguT_hi[GUN*DD],   g_wguT_lo[GUN*DD];
__device__ __nv_bfloat16 g_wdT_hi[DD*IPAD],   g_wdT_lo[DD*IPAD];
__device__ float         g_bqkv[QKVN];

// ---------------- helpers ----------------
__device__ __forceinline__ uint32_t smem_u32(const void* p){
    uint32_t r;
    asm("{ .reg .u64 t; cvta.to.shared.u64 t, %1; cvt.u32.u64 %0, t; }" : "=r"(r) : "l"(p));
    return r;
}
#define SWZ64(x)  ((x) ^ (((x) >> 3) & 0x30))
#define SWZ128(x) ((x) ^ (((x) >> 3) & 0x70))

__device__ __forceinline__ void ldsm_x4(uint32_t* r, uint32_t a){
    asm volatile("ldmatrix.sync.aligned.m8n8.x4.shared.b16 {%0,%1,%2,%3}, [%4];"
        : "=r"(r[0]), "=r"(r[1]), "=r"(r[2]), "=r"(r[3]) : "r"(a));
}
__device__ __forceinline__ void ldsm_x4_t(uint32_t* r, uint32_t a){
    asm volatile("ldmatrix.sync.aligned.m8n8.x4.trans.shared.b16 {%0,%1,%2,%3}, [%4];"
        : "=r"(r[0]), "=r"(r[1]), "=r"(r[2]), "=r"(r[3]) : "r"(a));
}
__device__ __forceinline__ void mma_bf16(float* c, const uint32_t* a, uint32_t b0, uint32_t b1){
    asm volatile("mma.sync.aligned.m16n8k16.row.col.f32.bf16.bf16.f32 "
        "{%0,%1,%2,%3}, {%4,%5,%6,%7}, {%8,%9}, {%0,%1,%2,%3};"
        : "+f"(c[0]), "+f"(c[1]), "+f"(c[2]), "+f"(c[3])
        : "r"(a[0]), "r"(a[1]), "r"(a[2]), "r"(a[3]), "r"(b0), "r"(b1));
}
__device__ __forceinline__ uint32_t pack_bf16(float lo_elem, float hi_elem){
    uint32_t r;
    asm("cvt.rn.bf16x2.f32 %0, %1, %2;" : "=r"(r) : "f"(hi_elem), "f"(lo_elem));
    return r;
}
#define CPA16(d, g) asm volatile("cp.async.cg.shared.global [%0], [%1], 16;\n" :: "r"(d), "l"(g))
#define CPA_COMMIT() asm volatile("cp.async.commit_group;\n" ::: "memory")

// ---------------- HMMA GEMM ----------------
#define GBK 32
#define STAGES 4
#define TILEB (128*32*2)
#define STGB (4*TILEB)
#define GEMM_SMEM (STAGES*STGB)

__global__ __launch_bounds__(256, 1)
void tc_gemm(const __nv_bfloat16* __restrict__ Ahi, const __nv_bfloat16* __restrict__ Alo,
             const __nv_bfloat16* __restrict__ Bhi, const __nv_bfloat16* __restrict__ Blo,
             const float* __restrict__ bias, const float* __restrict__ add,
             float* __restrict__ C, int K, int ldc,
             __nv_bfloat16* __restrict__ Ohi, __nv_bfloat16* __restrict__ Olo, int qscale_cols)
{
    extern __shared__ __align__(1024) char smem[];
    uint32_t sb = smem_u32(smem);
    int tid = threadIdx.x, wid = tid >> 5, lane = tid & 31;
    int m0 = blockIdx.y * 128, n0 = blockIdx.x * 128;
    int warp_m = wid & 3, warp_n = wid >> 2;

    const int KT = K / GBK;

    auto issue_loads = [&](int s, int kt){
        int k0 = kt * GBK;
        uint32_t stg = sb + s * STGB;
        #pragma unroll
        for (int t = 0; t < 4; t++) {
            const __nv_bfloat16* src = (t == 0 ? Ahi : t == 1 ? Alo : t == 2 ? Bhi : Blo);
            int rb = (t < 2 ? m0 : n0);
            #pragma unroll
            for (int i = 0; i < 2; i++) {
                int id = i * 256 + tid;
                int r = id >> 2, c = id & 3;
                const void* g = src + (size_t)(rb + r) * K + k0 + c * 8;
                uint32_t d = stg + t * TILEB + SWZ64((uint32_t)(r * 64 + c * 16));
                CPA16(d, g);
            }
        }
        CPA_COMMIT();
    };

    float acc[2][8][4];
    #pragma unroll
    for (int mt = 0; mt < 2; mt++)
        #pragma unroll
        for (int nt = 0; nt < 8; nt++)
            #pragma unroll
            for (int i = 0; i < 4; i++) acc[mt][nt][i] = 0.0f;

    issue_loads(0, 0);
    issue_loads(1, 1);
    issue_loads(2, 2);

    for (int kt = 0; kt < KT; kt++) {
        asm volatile("cp.async.wait_group 2;\n" ::: "memory");
        __syncthreads();
        if (kt + 3 < KT) issue_loads((kt + 3) % STAGES, kt + 3);

        uint32_t stg = sb + (kt % STAGES) * STGB;
        #pragma unroll
        for (int kk = 0; kk < 2; kk++) {
            uint32_t a_h[2][4], a_l[2][4];
            #pragma unroll
            for (int mt = 0; mt < 2; mt++) {
                int row = warp_m * 32 + mt * 16 + (lane & 15);
                uint32_t sw = SWZ64((uint32_t)(row * 64 + kk * 32 + (lane >> 4) * 16));
                ldsm_x4(a_h[mt], stg + sw);
                ldsm_x4(a_l[mt], stg + TILEB + sw);
            }
            uint32_t b_h[8][2], b_l[8][2];
            #pragma unroll
            for (int np = 0; np < 4; np++) {
                int nrow = warp_n * 64 + np * 16 + (lane & 7) + ((lane >> 4) << 3);
                uint32_t sw = SWZ64((uint32_t)(nrow * 64 + kk * 32 + ((lane >> 3) & 1) * 16));
                uint32_t t4[4];
                ldsm_x4(t4, stg + 2 * TILEB + sw);
                b_h[2*np][0] = t4[0]; b_h[2*np][1] = t4[1];
                b_h[2*np+1][0] = t4[2]; b_h[2*np+1][1] = t4[3];
                ldsm_x4(t4, stg + 3 * TILEB + sw);
                b_l[2*np][0] = t4[0]; b_l[2*np][1] = t4[1];
                b_l[2*np+1][0] = t4[2]; b_l[2*np+1][1] = t4[3];
            }
            #pragma unroll
            for (int mt = 0; mt < 2; mt++)
                #pragma unroll
                for (int nt = 0; nt < 8; nt++) {
                    mma_bf16(acc[mt][nt], a_h[mt], b_h[nt][0], b_h[nt][1]);
                    mma_bf16(acc[mt][nt], a_h[mt], b_l[nt][0], b_l[nt][1]);
                    mma_bf16(acc[mt][nt], a_l[mt], b_h[nt][0], b_h[nt][1]);
                }
        }
        __syncthreads();
    }

    #pragma unroll
    for (int mt = 0; mt < 2; mt++) {
        #pragma unroll
        for (int half = 0; half < 2; half++) {
            int r = m0 + warp_m * 32 + mt * 16 + (lane >> 2) + half * 8;
            size_t crow = (size_t)r * ldc;
            #pragma unroll
            for (int nt = 0; nt < 8; nt++) {
                int c = n0 + warp_n * 64 + nt * 8 + (lane & 3) * 2;
                float2 v;
                v.x = acc[mt][nt][half * 2 + 0];
                v.y = acc[mt][nt][half * 2 + 1];
                if (bias) { v.x += bias[c]; v.y += bias[c + 1]; }
                if (add) {
                    float2 a = *(const float2*)&add[crow + c];
                    v.x += a.x; v.y += a.y;
                }
                if (Ohi) {
                    if (c < qscale_cols) { v.x *= 0.125f; v.y *= 0.125f; }
                    uint32_t hp = pack_bf16(v.x, v.y);
                    *(uint32_t*)&Ohi[crow + c] = hp;
                    __nv_bfloat16* hb = (__nv_bfloat16*)&hp;
                    *(uint32_t*)&Olo[crow + c] = pack_bf16(v.x - __bfloat162float(hb[0]),
                                                           v.y - __bfloat162float(hb[1]));
                } else {
                    *(float2*)&C[crow + c] = v;
                }
            }
        }
    }
}

// ---------------- fused gate/up GEMM + SwiGLU + split ----------------
// Computes gate = A@Bg^T, up = A@Bu^T for the same 128-col tile, then
// act = silu(gate)*up, written as bf16 hi/lo. Bg rows n0.., Bu rows IPAD+n0..
#define MTILEB 8192
#define MSTGB (6*MTILEB)            // 49152: Ahi,Alo,Bg_hi,Bg_lo,Bu_hi,Bu_lo
#define MLP_SMEM (STAGES*MSTGB)     // 196608

__global__ __launch_bounds__(256, 1)
void tc_gemm_swiglu(const __nv_bfloat16* __restrict__ Ahi, const __nv_bfloat16* __restrict__ Alo,
                    const __nv_bfloat16* __restrict__ Whi, const __nv_bfloat16* __restrict__ Wlo,
                    __nv_bfloat16* __restrict__ Ohi, __nv_bfloat16* __restrict__ Olo)
{
    extern __shared__ __align__(1024) char smem[];
    uint32_t sb = smem_u32(smem);
    int tid = threadIdx.x, wid = tid >> 5, lane = tid & 31;
    int m0 = blockIdx.y * 128, n0 = blockIdx.x * 128;
    int warp_m = wid & 3, warp_n = wid >> 2;

    const int K = DD;
    const int KT = K / GBK;

    auto issue_loads = [&](int s, int kt){
        int k0 = kt * GBK;
        uint32_t stg = sb + s * MSTGB;
        #pragma unroll
        for (int t = 0; t < 6; t++) {
            const __nv_bfloat16* src =
                (t == 0 ? Ahi : t == 1 ? Alo : t == 2 ? Whi : t == 3 ? Wlo : t == 4 ? Whi : Wlo);
            int rb = (t < 2 ? m0 : (t < 4 ? n0 : IPAD + n0));
            #pragma unroll
            for (int i = 0; i < 2; i++) {
                int id = i * 256 + tid;
                int r = id >> 2, c = id & 3;
                const void* g = src + (size_t)(rb + r) * K + k0 + c * 8;
                uint32_t d = stg + t * MTILEB + SWZ64((uint32_t)(r * 64 + c * 16));
                CPA16(d, g);
            }
        }
        CPA_COMMIT();
    };

    float accg[2][8][4], accu[2][8][4];
    #pragma unroll
    for (int mt = 0; mt < 2; mt++)
        #pragma unroll
        for (int nt = 0; nt < 8; nt++)
            #pragma unroll
            for (int i = 0; i < 4; i++) { accg[mt][nt][i] = 0.0f; accu[mt][nt][i] = 0.0f; }

    issue_loads(0, 0);
    issue_loads(1, 1);
    issue_loads(2, 2);

    for (int kt = 0; kt < KT; kt++) {
        asm volatile("cp.async.wait_group 2;\n" ::: "memory");
        __syncthreads();
        if (kt + 3 < KT) issue_loads((kt + 3) % STAGES, kt + 3);

        uint32_t stg = sb + (kt % STAGES) * MSTGB;
        #pragma unroll
        for (int kk = 0; kk < 2; kk++) {
            uint32_t a_h[2][4], a_l[2][4];
            #pragma unroll
            for (int mt = 0; mt < 2; mt++) {
                int row = warp_m * 32 + mt * 16 + (lane & 15);
                uint32_t sw = SWZ64((uint32_t)(row * 64 + kk * 32 + (lane >> 4) * 16));
                ldsm_x4(a_h[mt], stg + sw);
                ldsm_x4(a_l[mt], stg + MTILEB + sw);
            }
            // gate then up, sharing A frags
            #pragma unroll
            for (int gu = 0; gu < 2; gu++) {
                uint32_t bh_off = stg + (2 + 2 * gu) * MTILEB;
                uint32_t bl_off = stg + (3 + 2 * gu) * MTILEB;
                #pragma unroll
                for (int np = 0; np < 4; np++) {
                    int nrow = warp_n * 64 + np * 16 + (lane & 7) + ((lane >> 4) << 3);
                    uint32_t sw = SWZ64((uint32_t)(nrow * 64 + kk * 32 + ((lane >> 3) & 1) * 16));
                    uint32_t th[4], tl[4];
                    ldsm_x4(th, bh_off + sw);
                    ldsm_x4(tl, bl_off + sw);
                    #pragma unroll
                    for (int mt = 0; mt < 2; mt++) {
                        float* c0 = (gu == 0 ? accg[mt][2*np]   : accu[mt][2*np]);
                        float* c1 = (gu == 0 ? accg[mt][2*np+1] : accu[mt][2*np+1]);
                        mma_bf16(c0, a_h[mt], th[0], th[1]);
                        mma_bf16(c0, a_h[mt], tl[0], tl[1]);
                        mma_bf16(c0, a_l[mt], th[0], th[1]);
                        mma_bf16(c1, a_h[mt], th[2], th[3]);
                        mma_bf16(c1, a_h[mt], tl[2], tl[3]);
                        mma_bf16(c1, a_l[mt], th[2], th[3]);
                    }
                }
            }
        }
        __syncthreads();
    }

    #pragma unroll
    for (int mt = 0; mt < 2; mt++) {
        #pragma unroll
        for (int half = 0; half < 2; half++) {
            int r = m0 + warp_m * 32 + mt * 16 + (lane >> 2) + half * 8;
            size_t crow = (size_t)r * IPAD;
            #pragma unroll
            for (int nt = 0; nt < 8; nt++) {
                int c = n0 + warp_n * 64 + nt * 8 + (lane & 3) * 2;
                float g0 = accg[mt][nt][half * 2 + 0];
                float g1 = accg[mt][nt][half * 2 + 1];
                float u0 = accu[mt][nt][half * 2 + 0];
                float u1 = accu[mt][nt][half * 2 + 1];
                float v0 = g0 / (1.0f + __expf(-g0)) * u0;
                float v1 = g1 / (1.0f + __expf(-g1)) * u1;
                uint32_t hp = pack_bf16(v0, v1);
                *(uint32_t*)&Ohi[crow + c] = hp;
                __nv_bfloat16* hb = (__nv_bfloat16*)&hp;
                *(uint32_t*)&Olo[crow + c] = pack_bf16(v0 - __bfloat162float(hb[0]),
                                                       v1 - __bfloat162float(hb[1]));
            }
        }
    }
}

// ---------------- FA2-style HMMA attention ----------------
#define AQ 128
#define AK 64
#define SM_QHI 0
#define SM_QLO 16384
#define SM_KV  32768
#define SO_KHI 0
#define SO_KLO 8192
#define SO_VHI 16384
#define SO_VLO 24576
#define KV_STG 32768
#define SM_KPM (SM_KV + 2*KV_STG)
#define ATTN_SMEM (SM_KPM + 128)

__global__ __launch_bounds__(256, 1)
void attn_mma_kernel(const __nv_bfloat16* __restrict__ qkv_hi,
                     const __nv_bfloat16* __restrict__ qkv_lo,
                     const unsigned char* __restrict__ kpm,
                     __nv_bfloat16* __restrict__ ohi, __nv_bfloat16* __restrict__ olo)
{
    extern __shared__ __align__(1024) char smem[];
    uint32_t sb = smem_u32(smem);
    int tid = threadIdx.x, wid = tid >> 5, lane = tid & 31;
    int qt = blockIdx.x, bh = blockIdx.y;
    int b = bh >> 4, h = bh & 15;
    size_t row0 = (size_t)(b * SS + qt * AQ);

    auto issue_kv = [&](int t){
        int s = t & 1;
        int j0 = t * AK;
        uint32_t stg = sb + SM_KV + s * KV_STG;
        #pragma unroll
        for (int i = 0; i < 2; i++) {
            int id = i * 256 + tid;
            int r = id >> 3, c = id & 7;
            size_t g = (size_t)(b * SS + j0 + r) * QKVN + h * HDD + c * 8;
            uint32_t sw = SWZ128((uint32_t)(r * 128 + c * 16));
            CPA16(stg + SO_KHI + sw, qkv_hi + g + 1024);
            CPA16(stg + SO_KLO + sw, qkv_lo + g + 1024);
            CPA16(stg + SO_VHI + sw, qkv_hi + g + 2048);
            CPA16(stg + SO_VLO + sw, qkv_lo + g + 2048);
        }
        if (tid < 4)
            CPA16(sb + SM_KPM + s * 64 + tid * 16, kpm + (size_t)b * SS + j0 + tid * 16);
        CPA_COMMIT();
    };

    const int T = 2 * qt + 2;

    issue_kv(0);
    #pragma unroll
    for (int i = 0; i < 4; i++) {
        int id = i * 256 + tid;
        int r = id >> 3, c = id & 7;
        size_t g = (row0 + r) * QKVN + h * HDD + c * 8;
        uint32_t sw = SWZ128((uint32_t)(r * 128 + c * 16));
        CPA16(sb + SM_QHI + sw, qkv_hi + g);
        CPA16(sb + SM_QLO + sw, qkv_lo + g);
    }
    CPA_COMMIT();
    issue_kv(1);

    asm volatile("cp.async.wait_group 1;\n" ::: "memory");
    __syncthreads();

    uint32_t qh[4][4], ql[4][4];
    {
        int row = wid * 16 + (lane & 15);
        #pragma unroll
        for (int kk = 0; kk < 4; kk++) {
            uint32_t sw = SWZ128((uint32_t)(row * 128 + kk * 32 + (lane >> 4) * 16));
            ldsm_x4(qh[kk], sb + SM_QHI + sw);
            ldsm_x4(ql[kk], sb + SM_QLO + sw);
        }
    }

    float slope = -exp2f(-0.5f * (float)(h + 1));
    float m[2] = {-1e30f, -1e30f}, l[2] = {0.0f, 0.0f};
    float o[8][4];
    #pragma unroll
    for (int nt = 0; nt < 8; nt++)
        #pragma unroll
        for (int i = 0; i < 4; i++) o[nt][i] = 0.0f;

    int r0 = wid * 16 + (lane >> 2);

    for (int t = 0; t < T; t++) {
        if (t > 0) {
            asm volatile("cp.async.wait_group 1;\n" ::: "memory");
            __syncthreads();
        }
        uint32_t stg = sb + SM_KV + (t & 1) * KV_STG;
        const unsigned char* kpms = (const unsigned char*)(smem + SM_KPM + (t & 1) * 64);
        int j0 = t * AK;
        bool diag = (t >= 2 * qt);

        float s[8][4];
        #pragma unroll
        for (int nt = 0; nt < 8; nt++)
            #pragma unroll
            for (int i = 0; i < 4; i++) s[nt][i] = 0.0f;

        #pragma unroll
        for (int kk = 0; kk < 4; kk++) {
            #pragma unroll
            for (int np = 0; np < 4; np++) {
                int nrow = np * 16 + (lane & 7) + ((lane >> 4) << 3);
                uint32_t sw = SWZ128((uint32_t)(nrow * 128 + kk * 32 + ((lane >> 3) & 1) * 16));
                uint32_t bhh[4], bll[4];
                ldsm_x4(bhh, stg + SO_KHI + sw);
                ldsm_x4(bll, stg + SO_KLO + sw);
                mma_bf16(s[2*np],   qh[kk], bhh[0], bhh[1]);
                mma_bf16(s[2*np],   qh[kk], bll[0], bll[1]);
                mma_bf16(s[2*np],   ql[kk], bhh[0], bhh[1]);
                mma_bf16(s[2*np+1], qh[kk], bhh[2], bhh[3]);
                mma_bf16(s[2*np+1], qh[kk], bll[2], bll[3]);
                mma_bf16(s[2*np+1], ql[kk], bhh[2], bhh[3]);
            }
        }

        float mt[2] = {-1e30f, -1e30f};
        #pragma unroll
        for (int nt = 0; nt < 8; nt++) {
            #pragma unroll
            for (int i = 0; i < 4; i++) {
                int half = i >> 1;
                int qi = qt * AQ + r0 + half * 8;
                int jj = j0 + nt * 8 + (lane & 3) * 2 + (i & 1);
                float sc = s[nt][i] + slope * fabsf((float)(qi - jj));
                if ((diag && jj > qi) || kpms[jj - j0]) sc = -1e30f;
                s[nt][i] = sc;
                mt[half] = fmaxf(mt[half], sc);
            }
        }
        #pragma unroll
        for (int half = 0; half < 2; half++) {
            mt[half] = fmaxf(mt[half], __shfl_xor_sync(0xffffffffu, mt[half], 1));
            mt[half] = fmaxf(mt[half], __shfl_xor_sync(0xffffffffu, mt[half], 2));
            float mnew = fmaxf(m[half], mt[half]);
            float corr = __expf(m[half] - mnew);
            m[half] = mnew;
            l[half] *= corr;
            #pragma unroll
            for (int nt = 0; nt < 8; nt++) {
                o[nt][half*2 + 0] *= corr;
                o[nt][half*2 + 1] *= corr;
            }
        }
        #pragma unroll
        for (int nt = 0; nt < 8; nt++) {
            #pragma unroll
            for (int i = 0; i < 4; i++) {
                float p = __expf(s[nt][i] - m[i >> 1]);
                s[nt][i] = p;
                l[i >> 1] += p;
            }
        }

        #pragma unroll
        for (int kc = 0; kc < 4; kc++) {
            uint32_t ph[4], pl[4];
            #pragma unroll
            for (int idx = 0; idx < 4; idx++) {
                int nt = 2 * kc + (idx >> 1);
                int ci = (idx & 1) * 2;
                float v0 = s[nt][ci], v1 = s[nt][ci + 1];
                ph[idx] = pack_bf16(v0, v1);
                __nv_bfloat16* hp = (__nv_bfloat16*)&ph[idx];
                pl[idx] = pack_bf16(v0 - __bfloat162float(hp[0]),
                                    v1 - __bfloat162float(hp[1]));
            }
            #pragma unroll
            for (int np = 0; np < 4; np++) {
                uint32_t sw = SWZ128((uint32_t)((kc * 16 + (lane & 15)) * 128 + np * 32 + (lane >> 4) * 16));
                uint32_t vh[4], vl[4];
                ldsm_x4_t(vh, stg + SO_VHI + sw);
                ldsm_x4_t(vl, stg + SO_VLO + sw);
                mma_bf16(o[2*np],   ph, vh[0], vh[1]);
                mma_bf16(o[2*np],   ph, vl[0], vl[1]);
                mma_bf16(o[2*np],   pl, vh[0], vh[1]);
                mma_bf16(o[2*np+1], ph, vh[2], vh[3]);
                mma_bf16(o[2*np+1], ph, vl[2], vl[3]);
                mma_bf16(o[2*np+1], pl, vh[2], vh[3]);
            }
        }

        __syncthreads();
        if (t + 2 < T) issue_kv(t + 2);
    }

    float inv[2];
    #pragma unroll
    for (int half = 0; half < 2; half++) {
        float ls = l[half];
        ls += __shfl_xor_sync(0xffffffffu, ls, 1);
        ls += __shfl_xor_sync(0xffffffffu, ls, 2);
        inv[half] = 1.0f / ls;
    }
    #pragma unroll
    for (int nt = 0; nt < 8; nt++) {
        #pragma unroll
        for (int half = 0; half < 2; half++) {
            int row = qt * AQ + wid * 16 + (lane >> 2) + half * 8;
            int col = h * HDD + nt * 8 + (lane & 3) * 2;
            size_t off = (size_t)(b * SS + row) * DD + col;
            float v0 = o[nt][half*2 + 0] * inv[half];
            float v1 = o[nt][half*2 + 1] * inv[half];
            uint32_t hp = pack_bf16(v0, v1);
            *(uint32_t*)&ohi[off] = hp;
            __nv_bfloat16* hb = (__nv_bfloat16*)&hp;
            *(uint32_t*)&olo[off] = pack_bf16(v0 - __bfloat162float(hb[0]),
                                              v1 - __bfloat162float(hb[1]));
        }
    }
}

// ---------------- RMSNorm + split ----------------
__global__ __launch_bounds__(256)
void rmsnorm_split_kernel(const float* __restrict__ x, const float* __restrict__ w,
                          __nv_bfloat16* __restrict__ ohi, __nv_bfloat16* __restrict__ olo)
{
    int row = blockIdx.x;
    const float* xr = x + (size_t)row * DD;
    int t = threadIdx.x;

    float v0 = xr[t], v1 = xr[t + 256], v2 = xr[t + 512], v3 = xr[t + 768];
    float ss = v0*v0 + v1*v1 + v2*v2 + v3*v3;
    #pragma unroll
    for (int off = 16; off; off >>= 1) ss += __shfl_xor_sync(0xffffffffu, ss, off);
    __shared__ float red[8];
    int wid = t >> 5, lid = t & 31;
    if (lid == 0) red[wid] = ss;
    __syncthreads();
    float tot = red[0]+red[1]+red[2]+red[3]+red[4]+red[5]+red[6]+red[7];
    float inv = rsqrtf(tot * (1.0f / (float)DD) + 1e-6f);

    size_t base = (size_t)row * DD;
    #pragma unroll
    for (int i = 0; i < 4; i++) {
        int c = t + i * 256;
        float val = w[c] * (i==0?v0:i==1?v1:i==2?v2:v3) * inv;
        __nv_bfloat16 hi = __float2bfloat16(val);
        ohi[base + c] = hi;
        olo[base + c] = __float2bfloat16(val - __bfloat162float(hi));
    }
}

// ---------------- weight transpose + split ----------------
__global__ __launch_bounds__(256)
void tsplit_kernel(const float* __restrict__ src, __nv_bfloat16* __restrict__ dhi,
                   __nv_bfloat16* __restrict__ dlo, int Ks, int Ns, int Kout)
{
    __shared__ float ts[32][33];
    int kt = blockIdx.x * 32, nt = blockIdx.y * 32;
    int tx = threadIdx.x & 31, ty = threadIdx.x >> 5;
    #pragma unroll
    for (int i = 0; i < 4; i++) {
        int k = kt + ty + 8 * i, n = nt + tx;
        ts[ty + 8 * i][tx] = (k < Ks && n < Ns) ? src[(size_t)k * Ns + n] : 0.0f;
    }
    __syncthreads();
    #pragma unroll
    for (int i = 0; i < 4; i++) {
        int n = nt + ty + 8 * i, k = kt + tx;
        float v = ts[tx][ty + 8 * i];
        __nv_bfloat16 hi = __float2bfloat16(v);
        dhi[(size_t)n * Kout + k] = hi;
        dlo[(size_t)n * Kout + k] = __float2bfloat16(v - __bfloat162float(hi));
    }
}

__global__ __launch_bounds__(256)
void bias_concat_kernel(const float* __restrict__ bq, const float* __restrict__ bk,
                        const float* __restrict__ bv, float* __restrict__ dst)
{
    int i = blockIdx.x * 256 + threadIdx.x;
    if (i < 1024)       dst[i] = bq[i];
    else if (i < 2048)  dst[i] = bk[i - 1024];
    else if (i < 3072)  dst[i] = bv[i - 2048];
}

// ---------------- launch ----------------
extern "C" void kernel_launch(void* const* d_in, const int* in_sizes, int n_in,
                              void* d_out, int out_size)
{
    const float* x      = (const float*)d_in[0];
    const float* wq     = (const float*)d_in[1];
    const float* bq     = (const float*)d_in[2];
    const float* wk     = (const float*)d_in[3];
    const float* bk     = (const float*)d_in[4];
    const float* wv     = (const float*)d_in[5];
    const float* bv     = (const float*)d_in[6];
    const float* wo     = (const float*)d_in[7];
    const float* bo     = (const float*)d_in[8];
    const float* w_gate = (const float*)d_in[9];
    const float* w_up   = (const float*)d_in[10];
    const float* w_down = (const float*)d_in[11];
    const float* ln1w   = (const float*)d_in[12];
    const float* ln2w   = (const float*)d_in[13];
    const unsigned char* kpm = (const unsigned char*)d_in[16];
    float* out = (float*)d_out;

    __nv_bfloat16 *h_hi, *h_lo, *qkv_hi, *qkv_lo, *attn_hi, *attn_lo, *h2_hi, *h2_lo, *act_hi, *act_lo;
    __nv_bfloat16 *wqkvT_hi, *wqkvT_lo, *woT_hi, *woT_lo, *wguT_hi, *wguT_lo, *wdT_hi, *wdT_lo;
    float *res1, *bqkv;
    cudaGetSymbolAddress((void**)&h_hi, g_h_hi);     cudaGetSymbolAddress((void**)&h_lo, g_h_lo);
    cudaGetSymbolAddress((void**)&qkv_hi, g_qkv_hi); cudaGetSymbolAddress((void**)&qkv_lo, g_qkv_lo);
    cudaGetSymbolAddress((void**)&attn_hi, g_attn_hi); cudaGetSymbolAddress((void**)&attn_lo, g_attn_lo);
    cudaGetSymbolAddress((void**)&res1, g_res1);
    cudaGetSymbolAddress((void**)&h2_hi, g_h2_hi);   cudaGetSymbolAddress((void**)&h2_lo, g_h2_lo);
    cudaGetSymbolAddress((void**)&act_hi, g_act_hi); cudaGetSymbolAddress((void**)&act_lo, g_act_lo);
    cudaGetSymbolAddress((void**)&wqkvT_hi, g_wqkvT_hi); cudaGetSymbolAddress((void**)&wqkvT_lo, g_wqkvT_lo);
    cudaGetSymbolAddress((void**)&woT_hi, g_woT_hi); cudaGetSymbolAddress((void**)&woT_lo, g_woT_lo);
    cudaGetSymbolAddress((void**)&wguT_hi, g_wguT_hi); cudaGetSymbolAddress((void**)&wguT_lo, g_wguT_lo);
    cudaGetSymbolAddress((void**)&wdT_hi, g_wdT_hi); cudaGetSymbolAddress((void**)&wdT_lo, g_wdT_lo);
    cudaGetSymbolAddress((void**)&bqkv, g_bqkv);

    cudaFuncSetAttribute(tc_gemm, cudaFuncAttributeMaxDynamicSharedMemorySize, GEMM_SMEM);
    cudaFuncSetAttribute(tc_gemm_swiglu, cudaFuncAttributeMaxDynamicSharedMemorySize, MLP_SMEM);
    cudaFuncSetAttribute(attn_mma_kernel, cudaFuncAttributeMaxDynamicSharedMemorySize, ATTN_SMEM);

    // weight prep
    tsplit_kernel<<<dim3(32, 32), 256>>>(wq, wqkvT_hi,               wqkvT_lo,               1024, 1024, 1024);
    tsplit_kernel<<<dim3(32, 32), 256>>>(wk, wqkvT_hi + 1024 * 1024, wqkvT_lo + 1024 * 1024, 1024, 1024, 1024);
    tsplit_kernel<<<dim3(32, 32), 256>>>(wv, wqkvT_hi + 2048 * 1024, wqkvT_lo + 2048 * 1024, 1024, 1024, 1024);
    tsplit_kernel<<<dim3(32, 32), 256>>>(wo, woT_hi, woT_lo, 1024, 1024, 1024);
    tsplit_kernel<<<dim3(32, 120), 256>>>(w_gate, wguT_hi,               wguT_lo,               1024, II, 1024);
    tsplit_kernel<<<dim3(32, 120), 256>>>(w_up,   wguT_hi + IPAD * 1024, wguT_lo + IPAD * 1024, 1024, II, 1024);
    tsplit_kernel<<<dim3(120, 32), 256>>>(w_down, wdT_hi, wdT_lo, II, 1024, IPAD);
    bias_concat_kernel<<<12, 256>>>(bq, bk, bv, bqkv);

    // 1) h = rmsnorm(x) -> hi/lo
    rmsnorm_split_kernel<<<MM, 256>>>(x, ln1w, h_hi, h_lo);
    // 2) qkv = h @ Wqkv^T + bqkv -> bf16 hi/lo (q pre-scaled by 0.125)
    tc_gemm<<<dim3(QKVN / 128, MM / 128), 256, GEMM_SMEM>>>(h_hi, h_lo, wqkvT_hi, wqkvT_lo,
        bqkv, nullptr, nullptr, DD, QKVN, qkv_hi, qkv_lo, 1024);
    // 3) attention (HMMA) -> attn hi/lo
    attn_mma_kernel<<<dim3(SS / AQ, BB * HH), 256, ATTN_SMEM>>>(qkv_hi, qkv_lo, kpm, attn_hi, attn_lo);
    // 4) res1 = attn @ Wo^T + bo + x
    tc_gemm<<<dim3(DD / 128, MM / 128), 256, GEMM_SMEM>>>(attn_hi, attn_lo, woT_hi, woT_lo,
        bo, x, res1, DD, DD, nullptr, nullptr, 0);
    // 5) h2 = rmsnorm(res1) -> hi/lo
    rmsnorm_split_kernel<<<MM, 256>>>(res1, ln2w, h2_hi, h2_lo);
    // 6+7) act = silu(h2@Wg^T) * (h2@Wu^T) -> bf16 hi/lo, fused
    tc_gemm_swiglu<<<dim3(IPAD / 128, MM / 128), 256, MLP_SMEM>>>(h2_hi, h2_lo,
        wguT_hi, wguT_lo, act_hi, act_lo);
    // 8) out = act @ Wdown^T + res1
    tc_gemm<<<dim3(DD / 128, MM / 128), 256, GEMM_SMEM>>>(act_hi, act_lo, wdT_hi, wdT_lo,
        nullptr, res1, out, IPAD, DD, nullptr, nullptr, 0);

    (void)in_sizes; (void)n_in; (void)out_size;
}